// round 1
// baseline (speedup 1.0000x reference)
#include <cuda_runtime.h>
#include <cuda_bf16.h>
#include <stdint.h>

#define TOKENS 65536   // B*N = 16*4096
#define FD     256
#define MSZ    4096
#define TOPK   8

// ---------------- device scratch (no allocations allowed) ----------------
__device__ float          g_q  [TOKENS * FD];   // projected q, fp32
__device__ __nv_bfloat16  g_qb [TOKENS * FD];   // projected q, bf16 (for MMA ranking)
__device__ __nv_bfloat16  g_kb [MSZ * FD];      // memory_keys bf16
__device__ int            g_idx[TOKENS * TOPK]; // top-8 indices per row
__device__ float          g_ret[TOKENS * FD];   // retrieved
__device__ float          g_h  [TOKENS * FD];   // hidden after relu

// ---------------- keys -> bf16 ----------------
__global__ void cvt_keys_kernel(const float* __restrict__ mk) {
    int i = blockIdx.x * blockDim.x + threadIdx.x;
    if (i < MSZ * FD) g_kb[i] = __float2bfloat16(mk[i]);
}

// ---------------- fp32 GEMM, 128x128 tile, 8x8 per thread ----------------
// MODE 0: qproj  (A=A1 param query, K=256, out=g_q fp32 + g_qb bf16)
// MODE 1: mlp1   (A=[A1 query | g_ret], K=512, relu, out=g_h)
// MODE 2: mlp2   (A=g_h, K=256, out=Cout param)
template<int MODE>
__global__ __launch_bounds__(256, 2)
void sgemm128(const float* __restrict__ A1,
              const float* __restrict__ Bw, const float* __restrict__ bias,
              float* __restrict__ Cout) {
    __shared__ float As[16][132];   // [k][m] transposed
    __shared__ float Bs[16][132];   // [k][n]
    const int tid  = threadIdx.x;
    const int row0 = blockIdx.y * 128;
    const int col0 = blockIdx.x * 128;
    const int tx = tid & 15, ty = tid >> 4;
    const int Ktot = (MODE == 1) ? 512 : 256;

    float acc[8][8];
    #pragma unroll
    for (int i = 0; i < 8; i++)
        #pragma unroll
        for (int j = 0; j < 8; j++) acc[i][j] = 0.f;

    const int ar = tid >> 1, ak = (tid & 1) * 8;  // A tile load: 128 rows x 16k
    const int bn = (tid & 15) * 8, bk = tid >> 4; // B tile load: 16k x 128n

    for (int kt = 0; kt < Ktot; kt += 16) {
        const float* Asrc;
        int kof;
        if (MODE == 1 && kt >= 256) { Asrc = g_ret; kof = kt - 256; }
        else if (MODE == 2)         { Asrc = g_h;   kof = kt; }
        else                        { Asrc = A1;    kof = kt; }
        float4 av0 = *(const float4*)&Asrc[(size_t)(row0 + ar) * FD + kof + ak];
        float4 av1 = *(const float4*)&Asrc[(size_t)(row0 + ar) * FD + kof + ak + 4];
        float4 bv0 = *(const float4*)&Bw[(size_t)(kt + bk) * FD + col0 + bn];
        float4 bv1 = *(const float4*)&Bw[(size_t)(kt + bk) * FD + col0 + bn + 4];
        __syncthreads();
        As[ak + 0][ar] = av0.x; As[ak + 1][ar] = av0.y;
        As[ak + 2][ar] = av0.z; As[ak + 3][ar] = av0.w;
        As[ak + 4][ar] = av1.x; As[ak + 5][ar] = av1.y;
        As[ak + 6][ar] = av1.z; As[ak + 7][ar] = av1.w;
        *(float4*)&Bs[bk][bn]     = bv0;
        *(float4*)&Bs[bk][bn + 4] = bv1;
        __syncthreads();
        #pragma unroll
        for (int k = 0; k < 16; k++) {
            float a[8], b[8];
            *(float4*)&a[0] = *(float4*)&As[k][ty * 8];
            *(float4*)&a[4] = *(float4*)&As[k][ty * 8 + 4];
            *(float4*)&b[0] = *(float4*)&Bs[k][tx * 8];
            *(float4*)&b[4] = *(float4*)&Bs[k][tx * 8 + 4];
            #pragma unroll
            for (int i = 0; i < 8; i++)
                #pragma unroll
                for (int j = 0; j < 8; j++)
                    acc[i][j] = fmaf(a[i], b[j], acc[i][j]);
        }
    }

    float bv[8];
    #pragma unroll
    for (int j = 0; j < 8; j++) bv[j] = bias[col0 + tx * 8 + j];
    #pragma unroll
    for (int i = 0; i < 8; i++) {
        const int r = row0 + ty * 8 + i;
        float v[8];
        #pragma unroll
        for (int j = 0; j < 8; j++) {
            v[j] = acc[i][j] + bv[j];
            if (MODE == 1) v[j] = fmaxf(v[j], 0.f);
        }
        float* crow;
        if (MODE == 0)      crow = g_q  + (size_t)r * FD + col0 + tx * 8;
        else if (MODE == 1) crow = g_h  + (size_t)r * FD + col0 + tx * 8;
        else                crow = Cout + (size_t)r * FD + col0 + tx * 8;
        *(float4*)&crow[0] = *(float4*)&v[0];
        *(float4*)&crow[4] = *(float4*)&v[4];
        if (MODE == 0) {
            __nv_bfloat16* qb = g_qb + (size_t)r * FD + col0 + tx * 8;
            #pragma unroll
            for (int j = 0; j < 8; j++) qb[j] = __float2bfloat16(v[j]);
        }
    }
}

// ---------------- bf16 MMA sim + fused top-8 ----------------
__device__ __forceinline__ void mma16816(float* d, uint32_t a0, uint32_t a1,
                                         uint32_t a2, uint32_t a3,
                                         uint32_t b0, uint32_t b1) {
    asm volatile(
        "mma.sync.aligned.m16n8k16.row.col.f32.bf16.bf16.f32 "
        "{%0,%1,%2,%3}, {%4,%5,%6,%7}, {%8,%9}, {%0,%1,%2,%3};\n"
        : "+f"(d[0]), "+f"(d[1]), "+f"(d[2]), "+f"(d[3])
        : "r"(a0), "r"(a1), "r"(a2), "r"(a3), "r"(b0), "r"(b1));
}

// block = 256 thr (8 warps as 4m x 2n), row tile 64, key tile 128, K chunk 32
__global__ __launch_bounds__(256, 2)
void sim_topk_kernel() {
    __shared__ __nv_bfloat16 As[64][40];    // 64 rows x 32 k (pad 8)
    __shared__ __nv_bfloat16 Bs[128][40];   // 128 keys x 32 k
    __shared__ float simT[128][65];         // [key][row] transposed for scan

    const int tid  = threadIdx.x;
    const int lane = tid & 31;
    const int wid  = tid >> 5;
    const int wm = wid & 3, wn = wid >> 2;
    const int row0 = blockIdx.x * 64;

    float ts[8]; int ti[8];
    #pragma unroll
    for (int i = 0; i < 8; i++) { ts[i] = -3.4e38f; ti[i] = 0; }

    const int lar = tid >> 2, lak = (tid & 3) * 8;   // As loader
    const int lbr = tid >> 1, lbk = (tid & 1) * 16;  // Bs loader

    for (int mt = 0; mt < MSZ; mt += 128) {
        float acc[8][4];
        #pragma unroll
        for (int n = 0; n < 8; n++)
            #pragma unroll
            for (int i = 0; i < 4; i++) acc[n][i] = 0.f;

        for (int kt = 0; kt < FD; kt += 32) {
            __syncthreads();
            *(uint4*)&As[lar][lak]     = *(const uint4*)&g_qb[(size_t)(row0 + lar) * FD + kt + lak];
            *(uint4*)&Bs[lbr][lbk]     = *(const uint4*)&g_kb[(size_t)(mt + lbr) * FD + kt + lbk];
            *(uint4*)&Bs[lbr][lbk + 8] = *(const uint4*)&g_kb[(size_t)(mt + lbr) * FD + kt + lbk + 8];
            __syncthreads();
            #pragma unroll
            for (int ks = 0; ks < 2; ks++) {
                const int ar_ = wm * 16 + (lane >> 2);
                const int ak_ = ks * 16 + (lane & 3) * 2;
                uint32_t a0 = *(const uint32_t*)&As[ar_][ak_];
                uint32_t a1 = *(const uint32_t*)&As[ar_ + 8][ak_];
                uint32_t a2 = *(const uint32_t*)&As[ar_][ak_ + 8];
                uint32_t a3 = *(const uint32_t*)&As[ar_ + 8][ak_ + 8];
                #pragma unroll
                for (int nt = 0; nt < 8; nt++) {
                    const int bn_ = wn * 64 + nt * 8 + (lane >> 2);
                    uint32_t b0 = *(const uint32_t*)&Bs[bn_][ak_];
                    uint32_t b1 = *(const uint32_t*)&Bs[bn_][ak_ + 8];
                    mma16816(acc[nt], a0, a1, a2, a3, b0, b1);
                }
            }
        }
        __syncthreads();
        // store sim tile transposed [key][row] (bank-friendly scan)
        #pragma unroll
        for (int nt = 0; nt < 8; nt++) {
            const int c0 = wn * 64 + nt * 8 + (lane & 3) * 2;
            const int rw = wm * 16 + (lane >> 2);
            simT[c0][rw]         = acc[nt][0];
            simT[c0 + 1][rw]     = acc[nt][1];
            simT[c0][rw + 8]     = acc[nt][2];
            simT[c0 + 1][rw + 8] = acc[nt][3];
        }
        __syncthreads();
        // per-row running top-8 (thread tid owns row tid); mostly 1 compare/val
        if (tid < 64) {
            #pragma unroll 4
            for (int c = 0; c < 128; c++) {
                float v = simT[c][tid];
                if (v > ts[7]) {
                    ts[7] = v; ti[7] = mt + c;
                    #pragma unroll
                    for (int j = 7; j > 0; j--) {
                        if (ts[j] > ts[j - 1]) {
                            float tf = ts[j]; ts[j] = ts[j - 1]; ts[j - 1] = tf;
                            int   tt = ti[j]; ti[j] = ti[j - 1]; ti[j - 1] = tt;
                        }
                    }
                }
            }
        }
    }
    if (tid < 64) {
        #pragma unroll
        for (int i = 0; i < 8; i++)
            g_idx[(size_t)(row0 + tid) * TOPK + i] = ti[i];
    }
}

// ---------------- exact fp32 re-score + softmax + weighted gather ----------------
__global__ __launch_bounds__(256)
void retrieve_kernel(const float* __restrict__ keys, const float* __restrict__ vals) {
    const int gwarp = (int)((blockIdx.x * blockDim.x + threadIdx.x) >> 5);
    const int lane  = threadIdx.x & 31;
    if (gwarp >= TOKENS) return;

    const float* qrow = g_q + (size_t)gwarp * FD;
    float4 q1 = *(const float4*)&qrow[lane * 8];
    float4 q2 = *(const float4*)&qrow[lane * 8 + 4];

    int id[8];
    #pragma unroll
    for (int i = 0; i < 8; i++) id[i] = g_idx[(size_t)gwarp * TOPK + i];

    float s[8];
    #pragma unroll
    for (int i = 0; i < 8; i++) {
        const float* kr = keys + (size_t)id[i] * FD + lane * 8;
        float4 k1 = *(const float4*)&kr[0];
        float4 k2 = *(const float4*)&kr[4];
        float p = q1.x * k1.x + q1.y * k1.y + q1.z * k1.z + q1.w * k1.w
                + q2.x * k2.x + q2.y * k2.y + q2.z * k2.z + q2.w * k2.w;
        #pragma unroll
        for (int o = 16; o > 0; o >>= 1) p += __shfl_xor_sync(0xffffffffu, p, o);
        s[i] = p;
    }
    float mx = s[0];
    #pragma unroll
    for (int i = 1; i < 8; i++) mx = fmaxf(mx, s[i]);
    float z = 0.f;
    #pragma unroll
    for (int i = 0; i < 8; i++) { s[i] = __expf(s[i] - mx); z += s[i]; }
    const float rz = 1.f / z;

    float r[8];
    #pragma unroll
    for (int j = 0; j < 8; j++) r[j] = 0.f;
    #pragma unroll
    for (int i = 0; i < 8; i++) {
        const float w = s[i] * rz;
        const float* vr = vals + (size_t)id[i] * FD + lane * 8;
        float4 v1 = *(const float4*)&vr[0];
        float4 v2 = *(const float4*)&vr[4];
        r[0] = fmaf(w, v1.x, r[0]); r[1] = fmaf(w, v1.y, r[1]);
        r[2] = fmaf(w, v1.z, r[2]); r[3] = fmaf(w, v1.w, r[3]);
        r[4] = fmaf(w, v2.x, r[4]); r[5] = fmaf(w, v2.y, r[5]);
        r[6] = fmaf(w, v2.z, r[6]); r[7] = fmaf(w, v2.w, r[7]);
    }
    float* rrow = g_ret + (size_t)gwarp * FD + lane * 8;
    *(float4*)&rrow[0] = *(float4*)&r[0];
    *(float4*)&rrow[4] = *(float4*)&r[4];
}

// ---------------- launch ----------------
extern "C" void kernel_launch(void* const* d_in, const int* in_sizes, int n_in,
                              void* d_out, int out_size) {
    const float* query = (const float*)d_in[0];
    const float* mkeys = (const float*)d_in[1];
    const float* mvals = (const float*)d_in[2];
    const float* Wq    = (const float*)d_in[3];
    const float* bq    = (const float*)d_in[4];
    const float* W1    = (const float*)d_in[5];
    const float* b1    = (const float*)d_in[6];
    const float* W2    = (const float*)d_in[7];
    const float* b2    = (const float*)d_in[8];
    float* out = (float*)d_out;

    cvt_keys_kernel<<<(MSZ * FD + 255) / 256, 256>>>(mkeys);
    sgemm128<0><<<dim3(2, 512), 256>>>(query, Wq, bq, nullptr);   // q = query@Wq + bq
    sim_topk_kernel<<<TOKENS / 64, 256>>>();                      // top-8 per row
    retrieve_kernel<<<(TOKENS * 32) / 256, 256>>>(mkeys, mvals);  // softmax-weighted gather
    sgemm128<1><<<dim3(2, 512), 256>>>(query, W1, b1, nullptr);   // h = relu([q|ret]@W1+b1)
    sgemm128<2><<<dim3(2, 512), 256>>>(nullptr, W2, b2, out);     // out = h@W2 + b2
}

// round 5
// speedup vs baseline: 1.1105x; 1.1105x over previous
#include <cuda_runtime.h>
#include <cuda_bf16.h>
#include <stdint.h>

#define TOKENS 65536   // B*N = 16*4096
#define FD     256
#define MSZ    4096
#define TOPK   8

// ---------------- device scratch (referenced ONLY from device code) ----------------
__device__ float          g_q   [TOKENS * FD];   // projected q, fp32 (exact rescore)
__device__ __nv_bfloat16  g_qb  [TOKENS * FD];   // projected q, bf16 (MMA ranking)
__device__ __nv_bfloat16  g_kb  [MSZ * FD];      // memory_keys bf16
__device__ int            g_idx [TOKENS * TOPK]; // top-8 indices per row
__device__ __nv_bfloat16  g_xhi [TOKENS * FD];   // raw query hi
__device__ __nv_bfloat16  g_xlo [TOKENS * FD];   // raw query lo
__device__ __nv_bfloat16  g_rhi [TOKENS * FD];   // retrieved hi
__device__ __nv_bfloat16  g_rlo [TOKENS * FD];   // retrieved lo
__device__ __nv_bfloat16  g_hhi [TOKENS * FD];   // hidden (relu) hi
__device__ __nv_bfloat16  g_hlo [TOKENS * FD];   // hidden (relu) lo
__device__ __nv_bfloat16  g_WqThi[FD * FD],     g_WqTlo[FD * FD];       // [n][k]
__device__ __nv_bfloat16  g_W1Thi[FD * 2 * FD], g_W1Tlo[FD * 2 * FD];   // [n][k], k=512
__device__ __nv_bfloat16  g_W2Thi[FD * FD],     g_W2Tlo[FD * FD];       // [n][k]

// ---------------- conversions ----------------
__global__ void cvt_keys_kernel(const float* __restrict__ mk) {
    int i = blockIdx.x * blockDim.x + threadIdx.x;
    if (i < MSZ * FD) g_kb[i] = __float2bfloat16(mk[i]);
}

__global__ void cvt_query_split_kernel(const float* __restrict__ src) {
    int i = blockIdx.x * blockDim.x + threadIdx.x;
    if (i < TOKENS * FD) {
        float x = src[i];
        __nv_bfloat16 h = __float2bfloat16(x);
        g_xhi[i] = h;
        g_xlo[i] = __float2bfloat16(x - __bfloat162float(h));
    }
}

// W is [K][N] row-major; write W^T split as [n][k]. WSEL: 0=Wq, 1=W1, 2=W2.
template<int WSEL>
__global__ void cvt_wT_kernel(const float* __restrict__ W) {
    const int K = (WSEL == 1) ? 2 * FD : FD;
    const int N = FD;
    int o = blockIdx.x * blockDim.x + threadIdx.x;
    if (o < K * N) {
        int n = o / K, k = o - n * K;
        float x = W[(size_t)k * N + n];
        __nv_bfloat16 h = __float2bfloat16(x);
        __nv_bfloat16 l = __float2bfloat16(x - __bfloat162float(h));
        if (WSEL == 0)      { g_WqThi[o] = h; g_WqTlo[o] = l; }
        else if (WSEL == 1) { g_W1Thi[o] = h; g_W1Tlo[o] = l; }
        else                { g_W2Thi[o] = h; g_W2Tlo[o] = l; }
    }
}

// ---------------- mma helper ----------------
__device__ __forceinline__ void mma16816(float* d, uint32_t a0, uint32_t a1,
                                         uint32_t a2, uint32_t a3,
                                         uint32_t b0, uint32_t b1) {
    asm volatile(
        "mma.sync.aligned.m16n8k16.row.col.f32.bf16.bf16.f32 "
        "{%0,%1,%2,%3}, {%4,%5,%6,%7}, {%8,%9}, {%0,%1,%2,%3};\n"
        : "+f"(d[0]), "+f"(d[1]), "+f"(d[2]), "+f"(d[3])
        : "r"(a0), "r"(a1), "r"(a2), "r"(a3), "r"(b0), "r"(b1));
}

// ---------------- split-bf16 tensor-core GEMM ----------------
// C[M,N] = A[M,K] @ B[K,N], A/B split (hi+lo), fp32 accum, 3 MMAs per step.
// block: 256 thr (8 warps, 4m x 2n). Tile 128x128, warp tile 32x64, K chunk 32.
// MODE 0: qproj (A=g_x*, B=WqT, K=256) -> g_q fp32 + g_qb bf16
// MODE 1: mlp1  (A=[g_x*|g_r*],B=W1T, K=512) -> relu -> g_hhi/g_hlo
// MODE 2: mlp2  (A=g_h*, B=W2T, K=256) -> Cout fp32
template<int MODE>
__global__ __launch_bounds__(256, 1)
void bgemm(const float* __restrict__ bias, float* __restrict__ Cout) {
    __shared__ __nv_bfloat16 As[2][128][40];  // [hi/lo][row][k]
    __shared__ __nv_bfloat16 Bs[2][128][40];  // [hi/lo][n][k]

    const int tid  = threadIdx.x;
    const int lane = tid & 31;
    const int wid  = tid >> 5;
    const int wm = wid & 3, wn = wid >> 2;
    const int row0 = blockIdx.y * 128;
    const int col0 = blockIdx.x * 128;
    const int Ktot = (MODE == 1) ? 512 : 256;

    const __nv_bfloat16* BThi = (MODE == 0) ? g_WqThi : (MODE == 1) ? g_W1Thi : g_W2Thi;
    const __nv_bfloat16* BTlo = (MODE == 0) ? g_WqTlo : (MODE == 1) ? g_W1Tlo : g_W2Tlo;

    float acc[2][8][4];
    #pragma unroll
    for (int mf = 0; mf < 2; mf++)
        #pragma unroll
        for (int nt = 0; nt < 8; nt++)
            #pragma unroll
            for (int i = 0; i < 4; i++) acc[mf][nt][i] = 0.f;

    const int lr = tid >> 1;          // 0..127
    const int lk = (tid & 1) * 16;    // 0 or 16

    for (int kt = 0; kt < Ktot; kt += 32) {
        const __nv_bfloat16 *ah, *al;
        int kof;
        if (MODE == 1 && kt >= 256) { ah = g_rhi; al = g_rlo; kof = kt - 256; }
        else if (MODE == 2)         { ah = g_hhi; al = g_hlo; kof = kt; }
        else                        { ah = g_xhi; al = g_xlo; kof = kt; }
        const size_t aoff = (size_t)(row0 + lr) * FD + kof + lk;
        const size_t boff = (size_t)(col0 + lr) * Ktot + kt + lk;
        uint4 ah0 = *(const uint4*)&ah[aoff];
        uint4 ah1 = *(const uint4*)&ah[aoff + 8];
        uint4 al0 = *(const uint4*)&al[aoff];
        uint4 al1 = *(const uint4*)&al[aoff + 8];
        uint4 bh0 = *(const uint4*)&BThi[boff];
        uint4 bh1 = *(const uint4*)&BThi[boff + 8];
        uint4 bl0 = *(const uint4*)&BTlo[boff];
        uint4 bl1 = *(const uint4*)&BTlo[boff + 8];
        __syncthreads();
        *(uint4*)&As[0][lr][lk]     = ah0;
        *(uint4*)&As[0][lr][lk + 8] = ah1;
        *(uint4*)&As[1][lr][lk]     = al0;
        *(uint4*)&As[1][lr][lk + 8] = al1;
        *(uint4*)&Bs[0][lr][lk]     = bh0;
        *(uint4*)&Bs[0][lr][lk + 8] = bh1;
        *(uint4*)&Bs[1][lr][lk]     = bl0;
        *(uint4*)&Bs[1][lr][lk + 8] = bl1;
        __syncthreads();

        #pragma unroll
        for (int ks = 0; ks < 2; ks++) {
            const int ak_ = ks * 16 + (lane & 3) * 2;
            uint32_t fah[2][4], fal[2][4];
            #pragma unroll
            for (int mf = 0; mf < 2; mf++) {
                const int r = wm * 32 + mf * 16 + (lane >> 2);
                fah[mf][0] = *(const uint32_t*)&As[0][r][ak_];
                fah[mf][1] = *(const uint32_t*)&As[0][r + 8][ak_];
                fah[mf][2] = *(const uint32_t*)&As[0][r][ak_ + 8];
                fah[mf][3] = *(const uint32_t*)&As[0][r + 8][ak_ + 8];
                fal[mf][0] = *(const uint32_t*)&As[1][r][ak_];
                fal[mf][1] = *(const uint32_t*)&As[1][r + 8][ak_];
                fal[mf][2] = *(const uint32_t*)&As[1][r][ak_ + 8];
                fal[mf][3] = *(const uint32_t*)&As[1][r + 8][ak_ + 8];
            }
            #pragma unroll
            for (int nt = 0; nt < 8; nt++) {
                const int bn_ = wn * 64 + nt * 8 + (lane >> 2);
                uint32_t fbh0 = *(const uint32_t*)&Bs[0][bn_][ak_];
                uint32_t fbh1 = *(const uint32_t*)&Bs[0][bn_][ak_ + 8];
                uint32_t fbl0 = *(const uint32_t*)&Bs[1][bn_][ak_];
                uint32_t fbl1 = *(const uint32_t*)&Bs[1][bn_][ak_ + 8];
                #pragma unroll
                for (int mf = 0; mf < 2; mf++) {
                    mma16816(acc[mf][nt], fah[mf][0], fah[mf][1], fah[mf][2], fah[mf][3], fbh0, fbh1);
                    mma16816(acc[mf][nt], fah[mf][0], fah[mf][1], fah[mf][2], fah[mf][3], fbl0, fbl1);
                    mma16816(acc[mf][nt], fal[mf][0], fal[mf][1], fal[mf][2], fal[mf][3], fbh0, fbh1);
                }
            }
        }
    }

    // epilogue
    #pragma unroll
    for (int nt = 0; nt < 8; nt++) {
        const int col_g = col0 + wn * 64 + nt * 8 + (lane & 3) * 2;
        const float b0 = bias[col_g], b1 = bias[col_g + 1];
        #pragma unroll
        for (int mf = 0; mf < 2; mf++) {
            #pragma unroll
            for (int half = 0; half < 2; half++) {
                const int row_g = row0 + wm * 32 + mf * 16 + (lane >> 2) + half * 8;
                float v0 = acc[mf][nt][half * 2 + 0] + b0;
                float v1 = acc[mf][nt][half * 2 + 1] + b1;
                const size_t o = (size_t)row_g * FD + col_g;
                if (MODE == 0) {
                    g_q[o] = v0; g_q[o + 1] = v1;
                    __nv_bfloat162 p;
                    p.x = __float2bfloat16(v0); p.y = __float2bfloat16(v1);
                    *(__nv_bfloat162*)&g_qb[o] = p;
                } else if (MODE == 1) {
                    v0 = fmaxf(v0, 0.f); v1 = fmaxf(v1, 0.f);
                    __nv_bfloat162 ph, pl;
                    ph.x = __float2bfloat16(v0); ph.y = __float2bfloat16(v1);
                    pl.x = __float2bfloat16(v0 - __bfloat162float(ph.x));
                    pl.y = __float2bfloat16(v1 - __bfloat162float(ph.y));
                    *(__nv_bfloat162*)&g_hhi[o] = ph;
                    *(__nv_bfloat162*)&g_hlo[o] = pl;
                } else {
                    Cout[o] = v0; Cout[o + 1] = v1;
                }
            }
        }
    }
}

// ---------------- bf16 MMA sim + fused top-8 ----------------
__global__ __launch_bounds__(256, 2)
void sim_topk_kernel() {
    __shared__ __nv_bfloat16 As[64][40];
    __shared__ __nv_bfloat16 Bs[128][40];
    __shared__ float simT[128][65];

    const int tid  = threadIdx.x;
    const int lane = tid & 31;
    const int wid  = tid >> 5;
    const int wm = wid & 3, wn = wid >> 2;
    const int row0 = blockIdx.x * 64;

    float ts[8]; int ti[8];
    #pragma unroll
    for (int i = 0; i < 8; i++) { ts[i] = -3.4e38f; ti[i] = 0; }

    const int lar = tid >> 2, lak = (tid & 3) * 8;
    const int lbr = tid >> 1, lbk = (tid & 1) * 16;

    for (int mt = 0; mt < MSZ; mt += 128) {
        float acc[8][4];
        #pragma unroll
        for (int n = 0; n < 8; n++)
            #pragma unroll
            for (int i = 0; i < 4; i++) acc[n][i] = 0.f;

        for (int kt = 0; kt < FD; kt += 32) {
            __syncthreads();
            *(uint4*)&As[lar][lak]     = *(const uint4*)&g_qb[(size_t)(row0 + lar) * FD + kt + lak];
            *(uint4*)&Bs[lbr][lbk]     = *(const uint4*)&g_kb[(size_t)(mt + lbr) * FD + kt + lbk];
            *(uint4*)&Bs[lbr][lbk + 8] = *(const uint4*)&g_kb[(size_t)(mt + lbr) * FD + kt + lbk + 8];
            __syncthreads();
            #pragma unroll
            for (int ks = 0; ks < 2; ks++) {
                const int ar_ = wm * 16 + (lane >> 2);
                const int ak_ = ks * 16 + (lane & 3) * 2;
                uint32_t a0 = *(const uint32_t*)&As[ar_][ak_];
                uint32_t a1 = *(const uint32_t*)&As[ar_ + 8][ak_];
                uint32_t a2 = *(const uint32_t*)&As[ar_][ak_ + 8];
                uint32_t a3 = *(const uint32_t*)&As[ar_ + 8][ak_ + 8];
                #pragma unroll
                for (int nt = 0; nt < 8; nt++) {
                    const int bn_ = wn * 64 + nt * 8 + (lane >> 2);
                    uint32_t b0 = *(const uint32_t*)&Bs[bn_][ak_];
                    uint32_t b1 = *(const uint32_t*)&Bs[bn_][ak_ + 8];
                    mma16816(acc[nt], a0, a1, a2, a3, b0, b1);
                }
            }
        }
        __syncthreads();
        #pragma unroll
        for (int nt = 0; nt < 8; nt++) {
            const int c0 = wn * 64 + nt * 8 + (lane & 3) * 2;
            const int rw = wm * 16 + (lane >> 2);
            simT[c0][rw]         = acc[nt][0];
            simT[c0 + 1][rw]     = acc[nt][1];
            simT[c0][rw + 8]     = acc[nt][2];
            simT[c0 + 1][rw + 8] = acc[nt][3];
        }
        __syncthreads();
        if (tid < 64) {
            #pragma unroll 4
            for (int c = 0; c < 128; c++) {
                float v = simT[c][tid];
                if (v > ts[7]) {
                    ts[7] = v; ti[7] = mt + c;
                    #pragma unroll
                    for (int j = 7; j > 0; j--) {
                        if (ts[j] > ts[j - 1]) {
                            float tf = ts[j]; ts[j] = ts[j - 1]; ts[j - 1] = tf;
                            int   tt = ti[j]; ti[j] = ti[j - 1]; ti[j - 1] = tt;
                        }
                    }
                }
            }
        }
    }
    if (tid < 64) {
        #pragma unroll
        for (int i = 0; i < 8; i++)
            g_idx[(size_t)(row0 + tid) * TOPK + i] = ti[i];
    }
}

// ---------------- exact fp32 re-score + softmax + weighted gather ----------------
__global__ __launch_bounds__(256)
void retrieve_kernel(const float* __restrict__ keys, const float* __restrict__ vals) {
    const int gwarp = (int)((blockIdx.x * blockDim.x + threadIdx.x) >> 5);
    const int lane  = threadIdx.x & 31;
    if (gwarp >= TOKENS) return;

    const float* qrow = g_q + (size_t)gwarp * FD;
    float4 q1 = *(const float4*)&qrow[lane * 8];
    float4 q2 = *(const float4*)&qrow[lane * 8 + 4];

    int id[8];
    #pragma unroll
    for (int i = 0; i < 8; i++) id[i] = g_idx[(size_t)gwarp * TOPK + i];

    float s[8];
    #pragma unroll
    for (int i = 0; i < 8; i++) {
        const float* kr = keys + (size_t)id[i] * FD + lane * 8;
        float4 k1 = *(const float4*)&kr[0];
        float4 k2 = *(const float4*)&kr[4];
        float p = q1.x * k1.x + q1.y * k1.y + q1.z * k1.z + q1.w * k1.w
                + q2.x * k2.x + q2.y * k2.y + q2.z * k2.z + q2.w * k2.w;
        #pragma unroll
        for (int o = 16; o > 0; o >>= 1) p += __shfl_xor_sync(0xffffffffu, p, o);
        s[i] = p;
    }
    float mx = s[0];
    #pragma unroll
    for (int i = 1; i < 8; i++) mx = fmaxf(mx, s[i]);
    float z = 0.f;
    #pragma unroll
    for (int i = 0; i < 8; i++) { s[i] = __expf(s[i] - mx); z += s[i]; }
    const float rz = 1.f / z;

    float r[8];
    #pragma unroll
    for (int j = 0; j < 8; j++) r[j] = 0.f;
    #pragma unroll
    for (int i = 0; i < 8; i++) {
        const float w = s[i] * rz;
        const float* vr = vals + (size_t)id[i] * FD + lane * 8;
        float4 v1 = *(const float4*)&vr[0];
        float4 v2 = *(const float4*)&vr[4];
        r[0] = fmaf(w, v1.x, r[0]); r[1] = fmaf(w, v1.y, r[1]);
        r[2] = fmaf(w, v1.z, r[2]); r[3] = fmaf(w, v1.w, r[3]);
        r[4] = fmaf(w, v2.x, r[4]); r[5] = fmaf(w, v2.y, r[5]);
        r[6] = fmaf(w, v2.z, r[6]); r[7] = fmaf(w, v2.w, r[7]);
    }
    __nv_bfloat16 hv[8], lv[8];
    #pragma unroll
    for (int j = 0; j < 8; j++) {
        hv[j] = __float2bfloat16(r[j]);
        lv[j] = __float2bfloat16(r[j] - __bfloat162float(hv[j]));
    }
    const size_t off = (size_t)gwarp * FD + lane * 8;
    *(uint4*)&g_rhi[off] = *(uint4*)hv;
    *(uint4*)&g_rlo[off] = *(uint4*)lv;
}

// ---------------- launch (only harness pointers cross the host/device line) ----------------
extern "C" void kernel_launch(void* const* d_in, const int* in_sizes, int n_in,
                              void* d_out, int out_size) {
    const float* query = (const float*)d_in[0];
    const float* mkeys = (const float*)d_in[1];
    const float* mvals = (const float*)d_in[2];
    const float* Wq    = (const float*)d_in[3];
    const float* bq    = (const float*)d_in[4];
    const float* W1    = (const float*)d_in[5];
    const float* b1    = (const float*)d_in[6];
    const float* W2    = (const float*)d_in[7];
    const float* b2    = (const float*)d_in[8];
    float* out = (float*)d_out;

    cvt_keys_kernel<<<(MSZ * FD + 255) / 256, 256>>>(mkeys);
    cvt_query_split_kernel<<<(TOKENS * FD + 255) / 256, 256>>>(query);
    cvt_wT_kernel<0><<<(FD * FD + 255) / 256, 256>>>(Wq);
    cvt_wT_kernel<1><<<(2 * FD * FD + 255) / 256, 256>>>(W1);
    cvt_wT_kernel<2><<<(FD * FD + 255) / 256, 256>>>(W2);

    bgemm<0><<<dim3(2, 512), 256>>>(bq, nullptr);                 // q = query@Wq+bq
    sim_topk_kernel<<<TOKENS / 64, 256>>>();                      // top-8 per row
    retrieve_kernel<<<(TOKENS * 32) / 256, 256>>>(mkeys, mvals);  // softmax gather
    bgemm<1><<<dim3(2, 512), 256>>>(b1, nullptr);                 // h = relu([x|ret]@W1+b1)
    bgemm<2><<<dim3(2, 512), 256>>>(b2, out);                     // out = h@W2+b2
}

// round 6
// speedup vs baseline: 1.5897x; 1.4315x over previous
#include <cuda_runtime.h>
#include <cuda_bf16.h>
#include <stdint.h>

#define TOKENS 65536   // B*N = 16*4096
#define FD     256
#define MSZ    4096
#define TOPK   8

// ---------------- device scratch (referenced ONLY from device code) ----------------
__device__ float          g_q   [TOKENS * FD];   // projected q, fp32 (exact rescore)
__device__ __nv_bfloat16  g_qb  [TOKENS * FD];   // projected q, bf16 (MMA ranking)
__device__ __nv_bfloat16  g_kb  [MSZ * FD];      // memory_keys bf16
__device__ int            g_idx [TOKENS * TOPK]; // top-8 indices per row
__device__ __nv_bfloat16  g_xhi [TOKENS * FD];   // raw query hi
__device__ __nv_bfloat16  g_xlo [TOKENS * FD];   // raw query lo
__device__ __nv_bfloat16  g_rhi [TOKENS * FD];   // retrieved hi
__device__ __nv_bfloat16  g_rlo [TOKENS * FD];   // retrieved lo
__device__ __nv_bfloat16  g_hhi [TOKENS * FD];   // hidden (relu) hi
__device__ __nv_bfloat16  g_hlo [TOKENS * FD];   // hidden (relu) lo
__device__ __nv_bfloat16  g_WqThi[FD * FD],     g_WqTlo[FD * FD];       // [n][k]
__device__ __nv_bfloat16  g_W1Thi[FD * 2 * FD], g_W1Tlo[FD * 2 * FD];   // [n][k], k=512
__device__ __nv_bfloat16  g_W2Thi[FD * FD],     g_W2Tlo[FD * FD];       // [n][k]

// ---------------- cp.async helpers ----------------
__device__ __forceinline__ void cp16(void* sdst, const void* gsrc) {
    uint32_t s = (uint32_t)__cvta_generic_to_shared(sdst);
    asm volatile("cp.async.cg.shared.global [%0], [%1], 16;\n" :: "r"(s), "l"(gsrc));
}
__device__ __forceinline__ void cp_commit() {
    asm volatile("cp.async.commit_group;\n" ::: "memory");
}
__device__ __forceinline__ void cp_wait1() {
    asm volatile("cp.async.wait_group 1;\n" ::: "memory");
}

// ---------------- conversions ----------------
// keys -> bf16, plus all three transposed split weights, in one kernel
__global__ __launch_bounds__(256)
void cvt_kw_kernel(const float* __restrict__ mk, const float* __restrict__ Wq,
                   const float* __restrict__ W1, const float* __restrict__ W2) {
    int i = blockIdx.x * blockDim.x + threadIdx.x;
    if (i < MSZ * FD) {
        g_kb[i] = __float2bfloat16(mk[i]);
        return;
    }
    int j = i - MSZ * FD;
    const float* W; __nv_bfloat16 *hiT, *loT; int K;
    if (j < FD * FD)               { W = Wq; hiT = g_WqThi; loT = g_WqTlo; K = FD; }
    else if (j < 3 * FD * FD)      { j -= FD * FD; W = W1; hiT = g_W1Thi; loT = g_W1Tlo; K = 2 * FD; }
    else if (j < 4 * FD * FD)      { j -= 3 * FD * FD; W = W2; hiT = g_W2Thi; loT = g_W2Tlo; K = FD; }
    else return;
    int n = j / K, k = j - n * K;
    float x = W[(size_t)k * FD + n];
    __nv_bfloat16 h = __float2bfloat16(x);
    hiT[j] = h;
    loT[j] = __float2bfloat16(x - __bfloat162float(h));
}

__global__ __launch_bounds__(256)
void cvt_query_split_kernel(const float* __restrict__ src) {
    int i = blockIdx.x * blockDim.x + threadIdx.x;
    if (i < TOKENS * FD) {
        float x = src[i];
        __nv_bfloat16 h = __float2bfloat16(x);
        g_xhi[i] = h;
        g_xlo[i] = __float2bfloat16(x - __bfloat162float(h));
    }
}

// ---------------- mma helper ----------------
__device__ __forceinline__ void mma16816(float* d, uint32_t a0, uint32_t a1,
                                         uint32_t a2, uint32_t a3,
                                         uint32_t b0, uint32_t b1) {
    asm volatile(
        "mma.sync.aligned.m16n8k16.row.col.f32.bf16.bf16.f32 "
        "{%0,%1,%2,%3}, {%4,%5,%6,%7}, {%8,%9}, {%0,%1,%2,%3};\n"
        : "+f"(d[0]), "+f"(d[1]), "+f"(d[2]), "+f"(d[3])
        : "r"(a0), "r"(a1), "r"(a2), "r"(a3), "r"(b0), "r"(b1));
}

// ---------------- split-bf16 tensor-core GEMM, 2-stage cp.async pipeline ----------------
// C[M,N] = A[M,K] @ B[K,N], A/B split (hi+lo), fp32 accum, 3 MMAs per step.
// block: 256 thr (8 warps, 4m x 2n). Tile 128x128, warp tile 32x64, K chunk 32.
// dyn smem: As[2st][2hl][128][40], Bs[2st][2hl][128][40] bf16 = 81920 B
#define BG_SMEM 81920

template<int MODE>
__device__ __forceinline__ void bgemm_load_chunk(__nv_bfloat16* As, __nv_bfloat16* Bs,
                                                 int st, int kt, int row0, int col0,
                                                 int tid, int Ktot) {
    const __nv_bfloat16 *ah, *al;
    int kof;
    if (MODE == 1 && kt >= 256) { ah = g_rhi; al = g_rlo; kof = kt - 256; }
    else if (MODE == 2)         { ah = g_hhi; al = g_hlo; kof = kt; }
    else                        { ah = g_xhi; al = g_xlo; kof = kt; }
    const __nv_bfloat16* bh = (MODE == 0) ? g_WqThi : (MODE == 1) ? g_W1Thi : g_W2Thi;
    const __nv_bfloat16* bl = (MODE == 0) ? g_WqTlo : (MODE == 1) ? g_W1Tlo : g_W2Tlo;
    const int lr = tid >> 1, lk = (tid & 1) * 16;
    const size_t aoff = (size_t)(row0 + lr) * FD + kof + lk;
    const size_t boff = (size_t)(col0 + lr) * Ktot + kt + lk;
    cp16(&As[((st * 2 + 0) * 128 + lr) * 40 + lk],     &ah[aoff]);
    cp16(&As[((st * 2 + 0) * 128 + lr) * 40 + lk + 8], &ah[aoff + 8]);
    cp16(&As[((st * 2 + 1) * 128 + lr) * 40 + lk],     &al[aoff]);
    cp16(&As[((st * 2 + 1) * 128 + lr) * 40 + lk + 8], &al[aoff + 8]);
    cp16(&Bs[((st * 2 + 0) * 128 + lr) * 40 + lk],     &bh[boff]);
    cp16(&Bs[((st * 2 + 0) * 128 + lr) * 40 + lk + 8], &bh[boff + 8]);
    cp16(&Bs[((st * 2 + 1) * 128 + lr) * 40 + lk],     &bl[boff]);
    cp16(&Bs[((st * 2 + 1) * 128 + lr) * 40 + lk + 8], &bl[boff + 8]);
}

template<int MODE>
__global__ __launch_bounds__(256, 1)
void bgemm(const float* __restrict__ bias, float* __restrict__ Cout) {
    extern __shared__ char dynsmem[];
    __nv_bfloat16* As = (__nv_bfloat16*)dynsmem;              // [st][hl][128][40]
    __nv_bfloat16* Bs = As + 2 * 2 * 128 * 40;

    const int tid  = threadIdx.x;
    const int lane = tid & 31;
    const int wid  = tid >> 5;
    const int wm = wid & 3, wn = wid >> 2;
    const int row0 = blockIdx.y * 128;
    const int col0 = blockIdx.x * 128;
    const int Ktot = (MODE == 1) ? 512 : 256;
    const int NC   = Ktot / 32;

    float acc[2][8][4];
    #pragma unroll
    for (int mf = 0; mf < 2; mf++)
        #pragma unroll
        for (int nt = 0; nt < 8; nt++)
            #pragma unroll
            for (int i = 0; i < 4; i++) acc[mf][nt][i] = 0.f;

    bgemm_load_chunk<MODE>(As, Bs, 0, 0, row0, col0, tid, Ktot);
    cp_commit();

    for (int c = 0; c < NC; c++) {
        const int st = c & 1;
        if (c + 1 < NC)
            bgemm_load_chunk<MODE>(As, Bs, (c + 1) & 1, (c + 1) * 32, row0, col0, tid, Ktot);
        cp_commit();
        cp_wait1();
        __syncthreads();

        #pragma unroll
        for (int ks = 0; ks < 2; ks++) {
            const int ak_ = ks * 16 + (lane & 3) * 2;
            uint32_t fah[2][4], fal[2][4];
            #pragma unroll
            for (int mf = 0; mf < 2; mf++) {
                const int r = wm * 32 + mf * 16 + (lane >> 2);
                fah[mf][0] = *(const uint32_t*)&As[((st * 2 + 0) * 128 + r) * 40 + ak_];
                fah[mf][1] = *(const uint32_t*)&As[((st * 2 + 0) * 128 + r + 8) * 40 + ak_];
                fah[mf][2] = *(const uint32_t*)&As[((st * 2 + 0) * 128 + r) * 40 + ak_ + 8];
                fah[mf][3] = *(const uint32_t*)&As[((st * 2 + 0) * 128 + r + 8) * 40 + ak_ + 8];
                fal[mf][0] = *(const uint32_t*)&As[((st * 2 + 1) * 128 + r) * 40 + ak_];
                fal[mf][1] = *(const uint32_t*)&As[((st * 2 + 1) * 128 + r + 8) * 40 + ak_];
                fal[mf][2] = *(const uint32_t*)&As[((st * 2 + 1) * 128 + r) * 40 + ak_ + 8];
                fal[mf][3] = *(const uint32_t*)&As[((st * 2 + 1) * 128 + r + 8) * 40 + ak_ + 8];
            }
            #pragma unroll
            for (int nt = 0; nt < 8; nt++) {
                const int bn_ = wn * 64 + nt * 8 + (lane >> 2);
                uint32_t fbh0 = *(const uint32_t*)&Bs[((st * 2 + 0) * 128 + bn_) * 40 + ak_];
                uint32_t fbh1 = *(const uint32_t*)&Bs[((st * 2 + 0) * 128 + bn_) * 40 + ak_ + 8];
                uint32_t fbl0 = *(const uint32_t*)&Bs[((st * 2 + 1) * 128 + bn_) * 40 + ak_];
                uint32_t fbl1 = *(const uint32_t*)&Bs[((st * 2 + 1) * 128 + bn_) * 40 + ak_ + 8];
                #pragma unroll
                for (int mf = 0; mf < 2; mf++) {
                    mma16816(acc[mf][nt], fah[mf][0], fah[mf][1], fah[mf][2], fah[mf][3], fbh0, fbh1);
                    mma16816(acc[mf][nt], fah[mf][0], fah[mf][1], fah[mf][2], fah[mf][3], fbl0, fbl1);
                    mma16816(acc[mf][nt], fal[mf][0], fal[mf][1], fal[mf][2], fal[mf][3], fbh0, fbh1);
                }
            }
        }
        __syncthreads();
    }

    // epilogue
    #pragma unroll
    for (int nt = 0; nt < 8; nt++) {
        const int col_g = col0 + wn * 64 + nt * 8 + (lane & 3) * 2;
        const float b0 = bias[col_g], b1 = bias[col_g + 1];
        #pragma unroll
        for (int mf = 0; mf < 2; mf++) {
            #pragma unroll
            for (int half = 0; half < 2; half++) {
                const int row_g = row0 + wm * 32 + mf * 16 + (lane >> 2) + half * 8;
                float v0 = acc[mf][nt][half * 2 + 0] + b0;
                float v1 = acc[mf][nt][half * 2 + 1] + b1;
                const size_t o = (size_t)row_g * FD + col_g;
                if (MODE == 0) {
                    g_q[o] = v0; g_q[o + 1] = v1;
                    __nv_bfloat162 p;
                    p.x = __float2bfloat16(v0); p.y = __float2bfloat16(v1);
                    *(__nv_bfloat162*)&g_qb[o] = p;
                } else if (MODE == 1) {
                    v0 = fmaxf(v0, 0.f); v1 = fmaxf(v1, 0.f);
                    __nv_bfloat162 ph, pl;
                    ph.x = __float2bfloat16(v0); ph.y = __float2bfloat16(v1);
                    pl.x = __float2bfloat16(v0 - __bfloat162float(ph.x));
                    pl.y = __float2bfloat16(v1 - __bfloat162float(ph.y));
                    *(__nv_bfloat162*)&g_hhi[o] = ph;
                    *(__nv_bfloat162*)&g_hlo[o] = pl;
                } else {
                    Cout[o] = v0; Cout[o + 1] = v1;
                }
            }
        }
    }
}

// ---------------- sim v2: persistent q tile + pipelined key tiles + split top-8 ----------------
// block 256 thr (8 warps, 4m x 2n). Row tile 128 (persistent in smem), key tile 128,
// K chunk 32 double-buffered. Scan: 2 threads/row, 64 keys each, merged at end.
// dyn smem: Aq[128][264] bf16 (67584) + Bs[2][128][40] bf16 (20480) + simT[128][132] f32 (67584)
#define SIM_AQ_OFF   0
#define SIM_BS_OFF   67584
#define SIM_ST_OFF   88064
#define SIM_SMEM     155648

__global__ __launch_bounds__(256, 1)
void sim_topk_kernel() {
    extern __shared__ char dynsmem[];
    __nv_bfloat16* Aq   = (__nv_bfloat16*)(dynsmem + SIM_AQ_OFF);   // [r][264]
    __nv_bfloat16* Bs   = (__nv_bfloat16*)(dynsmem + SIM_BS_OFF);   // [st][key][40]
    float*         simT = (float*)(dynsmem + SIM_ST_OFF);           // [c][132]

    const int tid  = threadIdx.x;
    const int lane = tid & 31;
    const int wid  = tid >> 5;
    const int wm = wid & 3, wn = wid >> 2;
    const int row0 = blockIdx.x * 128;
    const int srow = tid & 127, shalf = tid >> 7;

    float ts[8]; int ti[8];
    #pragma unroll
    for (int i = 0; i < 8; i++) { ts[i] = -3.4e38f; ti[i] = 0; }

    // persistent q tile: 128 rows x 256 k
    for (int i = tid; i < 128 * 32; i += 256) {
        const int r = i >> 5, seg = i & 31;
        cp16(&Aq[r * 264 + seg * 8], &g_qb[(size_t)(row0 + r) * FD + seg * 8]);
    }
    // first key chunk (stage 0)
    {
        const int mt = 0, kt = 0;
        #pragma unroll
        for (int j = 0; j < 2; j++) {
            const int idx = tid + j * 256;
            const int key = idx >> 2, seg = idx & 3;
            cp16(&Bs[(0 * 128 + key) * 40 + seg * 8],
                 &g_kb[(size_t)(mt * 128 + key) * FD + kt + seg * 8]);
        }
    }
    cp_commit();

    float acc[2][8][4];

    const int NGC = (MSZ / 128) * 8;   // 256 global chunks
    for (int gc = 0; gc < NGC; gc++) {
        const int st = gc & 1;
        if (gc + 1 < NGC) {
            const int mt2 = (gc + 1) >> 3, kt2 = ((gc + 1) & 7) * 32;
            const int st2 = (gc + 1) & 1;
            #pragma unroll
            for (int j = 0; j < 2; j++) {
                const int idx = tid + j * 256;
                const int key = idx >> 2, seg = idx & 3;
                cp16(&Bs[(st2 * 128 + key) * 40 + seg * 8],
                     &g_kb[(size_t)(mt2 * 128 + key) * FD + kt2 + seg * 8]);
            }
        }
        cp_commit();
        cp_wait1();
        __syncthreads();

        if ((gc & 7) == 0) {
            #pragma unroll
            for (int mf = 0; mf < 2; mf++)
                #pragma unroll
                for (int nt = 0; nt < 8; nt++)
                    #pragma unroll
                    for (int i = 0; i < 4; i++) acc[mf][nt][i] = 0.f;
        }

        const int kbase = (gc & 7) * 32;
        #pragma unroll
        for (int ks = 0; ks < 2; ks++) {
            const int ak = kbase + ks * 16 + (lane & 3) * 2;
            uint32_t a[2][4];
            #pragma unroll
            for (int mf = 0; mf < 2; mf++) {
                const int r = wm * 32 + mf * 16 + (lane >> 2);
                a[mf][0] = *(const uint32_t*)&Aq[r * 264 + ak];
                a[mf][1] = *(const uint32_t*)&Aq[(r + 8) * 264 + ak];
                a[mf][2] = *(const uint32_t*)&Aq[r * 264 + ak + 8];
                a[mf][3] = *(const uint32_t*)&Aq[(r + 8) * 264 + ak + 8];
            }
            const int bk = ks * 16 + (lane & 3) * 2;
            #pragma unroll
            for (int nt = 0; nt < 8; nt++) {
                const int bn = wn * 64 + nt * 8 + (lane >> 2);
                uint32_t b0 = *(const uint32_t*)&Bs[(st * 128 + bn) * 40 + bk];
                uint32_t b1 = *(const uint32_t*)&Bs[(st * 128 + bn) * 40 + bk + 8];
                mma16816(acc[0][nt], a[0][0], a[0][1], a[0][2], a[0][3], b0, b1);
                mma16816(acc[1][nt], a[1][0], a[1][1], a[1][2], a[1][3], b0, b1);
            }
        }

        if ((gc & 7) == 7) {
            const int mt = gc >> 3;
            __syncthreads();
            // store sim tile transposed [key][row]
            #pragma unroll
            for (int nt = 0; nt < 8; nt++) {
                const int c0 = wn * 64 + nt * 8 + (lane & 3) * 2;
                #pragma unroll
                for (int mf = 0; mf < 2; mf++) {
                    const int rw = wm * 32 + mf * 16 + (lane >> 2);
                    simT[c0 * 132 + rw]           = acc[mf][nt][0];
                    simT[(c0 + 1) * 132 + rw]     = acc[mf][nt][1];
                    simT[c0 * 132 + rw + 8]       = acc[mf][nt][2];
                    simT[(c0 + 1) * 132 + rw + 8] = acc[mf][nt][3];
                }
            }
            __syncthreads();
            // split scan: thread (srow, shalf) scans keys [shalf*64, shalf*64+64)
            #pragma unroll 4
            for (int cc = 0; cc < 64; cc++) {
                const int c = shalf * 64 + cc;
                float v = simT[c * 132 + srow];
                if (v > ts[7]) {
                    ts[7] = v; ti[7] = mt * 128 + c;
                    #pragma unroll
                    for (int j = 7; j > 0; j--) {
                        if (ts[j] > ts[j - 1]) {
                            float tf = ts[j]; ts[j] = ts[j - 1]; ts[j - 1] = tf;
                            int   tt = ti[j]; ti[j] = ti[j - 1]; ti[j - 1] = tt;
                        }
                    }
                }
            }
            __syncthreads();
        } else {
            __syncthreads();
        }
    }

    // merge the two half-lists per row (reuse simT as scratch)
    if (shalf == 1) {
        #pragma unroll
        for (int i = 0; i < 8; i++) {
            simT[srow * 16 + i]     = ts[i];
            simT[srow * 16 + 8 + i] = __int_as_float(ti[i]);
        }
    }
    __syncthreads();
    if (shalf == 0) {
        #pragma unroll
        for (int i = 0; i < 8; i++) {
            float v = simT[srow * 16 + i];
            int  ix = __float_as_int(simT[srow * 16 + 8 + i]);
            if (v > ts[7]) {
                ts[7] = v; ti[7] = ix;
                #pragma unroll
                for (int j = 7; j > 0; j--) {
                    if (ts[j] > ts[j - 1]) {
                        float tf = ts[j]; ts[j] = ts[j - 1]; ts[j - 1] = tf;
                        int   tt = ti[j]; ti[j] = ti[j - 1]; ti[j - 1] = tt;
                    }
                }
            }
        }
        #pragma unroll
        for (int i = 0; i < 8; i++)
            g_idx[(size_t)(row0 + srow) * TOPK + i] = ti[i];
    }
}

// ---------------- exact fp32 re-score + softmax + weighted gather ----------------
__global__ __launch_bounds__(256)
void retrieve_kernel(const float* __restrict__ keys, const float* __restrict__ vals) {
    const int gwarp = (int)((blockIdx.x * blockDim.x + threadIdx.x) >> 5);
    const int lane  = threadIdx.x & 31;
    if (gwarp >= TOKENS) return;

    const float* qrow = g_q + (size_t)gwarp * FD;
    float4 q1 = *(const float4*)&qrow[lane * 8];
    float4 q2 = *(const float4*)&qrow[lane * 8 + 4];

    int id[8];
    #pragma unroll
    for (int i = 0; i < 8; i++) id[i] = g_idx[(size_t)gwarp * TOPK + i];

    float s[8];
    #pragma unroll
    for (int i = 0; i < 8; i++) {
        const float* kr = keys + (size_t)id[i] * FD + lane * 8;
        float4 k1 = *(const float4*)&kr[0];
        float4 k2 = *(const float4*)&kr[4];
        float p = q1.x * k1.x + q1.y * k1.y + q1.z * k1.z + q1.w * k1.w
                + q2.x * k2.x + q2.y * k2.y + q2.z * k2.z + q2.w * k2.w;
        #pragma unroll
        for (int o = 16; o > 0; o >>= 1) p += __shfl_xor_sync(0xffffffffu, p, o);
        s[i] = p;
    }
    float mx = s[0];
    #pragma unroll
    for (int i = 1; i < 8; i++) mx = fmaxf(mx, s[i]);
    float z = 0.f;
    #pragma unroll
    for (int i = 0; i < 8; i++) { s[i] = __expf(s[i] - mx); z += s[i]; }
    const float rz = 1.f / z;

    float r[8];
    #pragma unroll
    for (int j = 0; j < 8; j++) r[j] = 0.f;
    #pragma unroll
    for (int i = 0; i < 8; i++) {
        const float w = s[i] * rz;
        const float* vr = vals + (size_t)id[i] * FD + lane * 8;
        float4 v1 = *(const float4*)&vr[0];
        float4 v2 = *(const float4*)&vr[4];
        r[0] = fmaf(w, v1.x, r[0]); r[1] = fmaf(w, v1.y, r[1]);
        r[2] = fmaf(w, v1.z, r[2]); r[3] = fmaf(w, v1.w, r[3]);
        r[4] = fmaf(w, v2.x, r[4]); r[5] = fmaf(w, v2.y, r[5]);
        r[6] = fmaf(w, v2.z, r[6]); r[7] = fmaf(w, v2.w, r[7]);
    }
    __nv_bfloat16 hv[8], lv[8];
    #pragma unroll
    for (int j = 0; j < 8; j++) {
        hv[j] = __float2bfloat16(r[j]);
        lv[j] = __float2bfloat16(r[j] - __bfloat162float(hv[j]));
    }
    const size_t off = (size_t)gwarp * FD + lane * 8;
    *(uint4*)&g_rhi[off] = *(uint4*)hv;
    *(uint4*)&g_rlo[off] = *(uint4*)lv;
}

// ---------------- launch ----------------
extern "C" void kernel_launch(void* const* d_in, const int* in_sizes, int n_in,
                              void* d_out, int out_size) {
    const float* query = (const float*)d_in[0];
    const float* mkeys = (const float*)d_in[1];
    const float* mvals = (const float*)d_in[2];
    const float* Wq    = (const float*)d_in[3];
    const float* bq    = (const float*)d_in[4];
    const float* W1    = (const float*)d_in[5];
    const float* b1    = (const float*)d_in[6];
    const float* W2    = (const float*)d_in[7];
    const float* b2    = (const float*)d_in[8];
    float* out = (float*)d_out;

    // opt-in to large dynamic smem (idempotent; not a stream op)
    cudaFuncSetAttribute(sim_topk_kernel, cudaFuncAttributeMaxDynamicSharedMemorySize, SIM_SMEM);
    cudaFuncSetAttribute(bgemm<0>, cudaFuncAttributeMaxDynamicSharedMemorySize, BG_SMEM);
    cudaFuncSetAttribute(bgemm<1>, cudaFuncAttributeMaxDynamicSharedMemorySize, BG_SMEM);
    cudaFuncSetAttribute(bgemm<2>, cudaFuncAttributeMaxDynamicSharedMemorySize, BG_SMEM);

    // launch order puts sim_topk at index 3 (ncu capture slot)
    cvt_kw_kernel<<<(MSZ * FD + 4 * FD * FD + 255) / 256, 256>>>(mkeys, Wq, W1, W2);   // 0
    cvt_query_split_kernel<<<(TOKENS * FD + 255) / 256, 256>>>(query);                 // 1
    bgemm<0><<<dim3(2, 512), 256, BG_SMEM>>>(bq, nullptr);                             // 2
    sim_topk_kernel<<<TOKENS / 128, 256, SIM_SMEM>>>();                                // 3
    retrieve_kernel<<<(TOKENS * 32) / 256, 256>>>(mkeys, mvals);                       // 4
    bgemm<1><<<dim3(2, 512), 256, BG_SMEM>>>(b1, nullptr);                             // 5
    bgemm<2><<<dim3(2, 512), 256, BG_SMEM>>>(b2, out);                                 // 6
}

// round 12
// speedup vs baseline: 1.7053x; 1.0727x over previous
#include <cuda_runtime.h>
#include <cuda_bf16.h>
#include <stdint.h>

#define TOKENS 65536   // B*N = 16*4096
#define FD     256
#define MSZ    4096
#define TOPK   8

// ---------------- device scratch (referenced ONLY from device code) ----------------
__device__ float          g_q   [TOKENS * FD];   // projected q, fp32 (exact rescore)
__device__ __nv_bfloat16  g_qb  [TOKENS * FD];   // projected q, bf16 (MMA ranking)
__device__ __nv_bfloat16  g_kb  [MSZ * FD];      // memory_keys bf16
__device__ int            g_idx [TOKENS * TOPK]; // top-8 indices per row
__device__ __nv_bfloat16  g_xhi [TOKENS * FD];   // raw query hi
__device__ __nv_bfloat16  g_xlo [TOKENS * FD];   // raw query lo
__device__ __nv_bfloat16  g_rhi [TOKENS * FD];   // retrieved hi
__device__ __nv_bfloat16  g_rlo [TOKENS * FD];   // retrieved lo
__device__ __nv_bfloat16  g_hhi [TOKENS * FD];   // hidden (relu) hi
__device__ __nv_bfloat16  g_hlo [TOKENS * FD];   // hidden (relu) lo
__device__ __nv_bfloat16  g_WqThi[FD * FD],     g_WqTlo[FD * FD];       // [n][k]
__device__ __nv_bfloat16  g_W1Thi[FD * 2 * FD], g_W1Tlo[FD * 2 * FD];   // [n][k], k=512
__device__ __nv_bfloat16  g_W2Thi[FD * FD],     g_W2Tlo[FD * FD];       // [n][k]

// ---------------- cp.async helpers ----------------
__device__ __forceinline__ void cp16(void* sdst, const void* gsrc) {
    uint32_t s = (uint32_t)__cvta_generic_to_shared(sdst);
    asm volatile("cp.async.cg.shared.global [%0], [%1], 16;\n" :: "r"(s), "l"(gsrc));
}
__device__ __forceinline__ void cp_commit() {
    asm volatile("cp.async.commit_group;\n" ::: "memory");
}
__device__ __forceinline__ void cp_wait1() {
    asm volatile("cp.async.wait_group 1;\n" ::: "memory");
}

// ---------------- conversions ----------------
__global__ __launch_bounds__(256)
void cvt_kw_kernel(const float* __restrict__ mk, const float* __restrict__ Wq,
                   const float* __restrict__ W1, const float* __restrict__ W2) {
    int i = blockIdx.x * blockDim.x + threadIdx.x;
    if (i < MSZ * FD) {
        g_kb[i] = __float2bfloat16(mk[i]);
        return;
    }
    int j = i - MSZ * FD;
    const float* W; __nv_bfloat16 *hiT, *loT; int K;
    if (j < FD * FD)          { W = Wq; hiT = g_WqThi; loT = g_WqTlo; K = FD; }
    else if (j < 3 * FD * FD) { j -= FD * FD; W = W1; hiT = g_W1Thi; loT = g_W1Tlo; K = 2 * FD; }
    else if (j < 4 * FD * FD) { j -= 3 * FD * FD; W = W2; hiT = g_W2Thi; loT = g_W2Tlo; K = FD; }
    else return;
    int n = j / K, k = j - n * K;
    float x = W[(size_t)k * FD + n];
    __nv_bfloat16 h = __float2bfloat16(x);
    hiT[j] = h;
    loT[j] = __float2bfloat16(x - __bfloat162float(h));
}

__global__ __launch_bounds__(256)
void cvt_query_split_kernel(const float* __restrict__ src) {
    int i = blockIdx.x * blockDim.x + threadIdx.x;
    if (i < TOKENS * FD) {
        float x = src[i];
        __nv_bfloat16 h = __float2bfloat16(x);
        g_xhi[i] = h;
        g_xlo[i] = __float2bfloat16(x - __bfloat162float(h));
    }
}

// ---------------- mma helper ----------------
__device__ __forceinline__ void mma16816(float* d, uint32_t a0, uint32_t a1,
                                         uint32_t a2, uint32_t a3,
                                         uint32_t b0, uint32_t b1) {
    asm volatile(
        "mma.sync.aligned.m16n8k16.row.col.f32.bf16.bf16.f32 "
        "{%0,%1,%2,%3}, {%4,%5,%6,%7}, {%8,%9}, {%0,%1,%2,%3};\n"
        : "+f"(d[0]), "+f"(d[1]), "+f"(d[2]), "+f"(d[3])
        : "r"(a0), "r"(a1), "r"(a2), "r"(a3), "r"(b0), "r"(b1));
}

// ---------------- split-bf16 tensor-core GEMM, 2-stage cp.async pipeline ----------------
#define BG_SMEM 81920

template<int MODE>
__device__ __forceinline__ void bgemm_load_chunk(__nv_bfloat16* As, __nv_bfloat16* Bs,
                                                 int st, int kt, int row0, int col0,
                                                 int tid, int Ktot) {
    const __nv_bfloat16 *ah, *al;
    int kof;
    if (MODE == 1 && kt >= 256) { ah = g_rhi; al = g_rlo; kof = kt - 256; }
    else if (MODE == 2)         { ah = g_hhi; al = g_hlo; kof = kt; }
    else                        { ah = g_xhi; al = g_xlo; kof = kt; }
    const __nv_bfloat16* bh = (MODE == 0) ? g_WqThi : (MODE == 1) ? g_W1Thi : g_W2Thi;
    const __nv_bfloat16* bl = (MODE == 0) ? g_WqTlo : (MODE == 1) ? g_W1Tlo : g_W2Tlo;
    const int lr = tid >> 1, lk = (tid & 1) * 16;
    const size_t aoff = (size_t)(row0 + lr) * FD + kof + lk;
    const size_t boff = (size_t)(col0 + lr) * Ktot + kt + lk;
    cp16(&As[((st * 2 + 0) * 128 + lr) * 40 + lk],     &ah[aoff]);
    cp16(&As[((st * 2 + 0) * 128 + lr) * 40 + lk + 8], &ah[aoff + 8]);
    cp16(&As[((st * 2 + 1) * 128 + lr) * 40 + lk],     &al[aoff]);
    cp16(&As[((st * 2 + 1) * 128 + lr) * 40 + lk + 8], &al[aoff + 8]);
    cp16(&Bs[((st * 2 + 0) * 128 + lr) * 40 + lk],     &bh[boff]);
    cp16(&Bs[((st * 2 + 0) * 128 + lr) * 40 + lk + 8], &bh[boff + 8]);
    cp16(&Bs[((st * 2 + 1) * 128 + lr) * 40 + lk],     &bl[boff]);
    cp16(&Bs[((st * 2 + 1) * 128 + lr) * 40 + lk + 8], &bl[boff + 8]);
}

template<int MODE>
__global__ __launch_bounds__(256, 2)
void bgemm(const float* __restrict__ bias, float* __restrict__ Cout) {
    extern __shared__ char dynsmem[];
    __nv_bfloat16* As = (__nv_bfloat16*)dynsmem;
    __nv_bfloat16* Bs = As + 2 * 2 * 128 * 40;

    const int tid  = threadIdx.x;
    const int lane = tid & 31;
    const int wid  = tid >> 5;
    const int wm = wid & 3, wn = wid >> 2;
    const int row0 = blockIdx.y * 128;
    const int col0 = blockIdx.x * 128;
    const int Ktot = (MODE == 1) ? 512 : 256;
    const int NC   = Ktot / 32;

    float acc[2][8][4];
    #pragma unroll
    for (int mf = 0; mf < 2; mf++)
        #pragma unroll
        for (int nt = 0; nt < 8; nt++)
            #pragma unroll
            for (int i = 0; i < 4; i++) acc[mf][nt][i] = 0.f;

    bgemm_load_chunk<MODE>(As, Bs, 0, 0, row0, col0, tid, Ktot);
    cp_commit();

    for (int c = 0; c < NC; c++) {
        const int st = c & 1;
        if (c + 1 < NC)
            bgemm_load_chunk<MODE>(As, Bs, (c + 1) & 1, (c + 1) * 32, row0, col0, tid, Ktot);
        cp_commit();
        cp_wait1();
        __syncthreads();

        #pragma unroll
        for (int ks = 0; ks < 2; ks++) {
            const int ak_ = ks * 16 + (lane & 3) * 2;
            uint32_t fah[2][4], fal[2][4];
            #pragma unroll
            for (int mf = 0; mf < 2; mf++) {
                const int r = wm * 32 + mf * 16 + (lane >> 2);
                fah[mf][0] = *(const uint32_t*)&As[((st * 2 + 0) * 128 + r) * 40 + ak_];
                fah[mf][1] = *(const uint32_t*)&As[((st * 2 + 0) * 128 + r + 8) * 40 + ak_];
                fah[mf][2] = *(const uint32_t*)&As[((st * 2 + 0) * 128 + r) * 40 + ak_ + 8];
                fah[mf][3] = *(const uint32_t*)&As[((st * 2 + 0) * 128 + r + 8) * 40 + ak_ + 8];
                fal[mf][0] = *(const uint32_t*)&As[((st * 2 + 1) * 128 + r) * 40 + ak_];
                fal[mf][1] = *(const uint32_t*)&As[((st * 2 + 1) * 128 + r + 8) * 40 + ak_];
                fal[mf][2] = *(const uint32_t*)&As[((st * 2 + 1) * 128 + r) * 40 + ak_ + 8];
                fal[mf][3] = *(const uint32_t*)&As[((st * 2 + 1) * 128 + r + 8) * 40 + ak_ + 8];
            }
            #pragma unroll
            for (int nt = 0; nt < 8; nt++) {
                const int bn_ = wn * 64 + nt * 8 + (lane >> 2);
                uint32_t fbh0 = *(const uint32_t*)&Bs[((st * 2 + 0) * 128 + bn_) * 40 + ak_];
                uint32_t fbh1 = *(const uint32_t*)&Bs[((st * 2 + 0) * 128 + bn_) * 40 + ak_ + 8];
                uint32_t fbl0 = *(const uint32_t*)&Bs[((st * 2 + 1) * 128 + bn_) * 40 + ak_];
                uint32_t fbl1 = *(const uint32_t*)&Bs[((st * 2 + 1) * 128 + bn_) * 40 + ak_ + 8];
                #pragma unroll
                for (int mf = 0; mf < 2; mf++) {
                    mma16816(acc[mf][nt], fah[mf][0], fah[mf][1], fah[mf][2], fah[mf][3], fbh0, fbh1);
                    mma16816(acc[mf][nt], fah[mf][0], fah[mf][1], fah[mf][2], fah[mf][3], fbl0, fbl1);
                    mma16816(acc[mf][nt], fal[mf][0], fal[mf][1], fal[mf][2], fal[mf][3], fbh0, fbh1);
                }
            }
        }
        __syncthreads();
    }

    #pragma unroll
    for (int nt = 0; nt < 8; nt++) {
        const int col_g = col0 + wn * 64 + nt * 8 + (lane & 3) * 2;
        const float b0 = bias[col_g], b1 = bias[col_g + 1];
        #pragma unroll
        for (int mf = 0; mf < 2; mf++) {
            #pragma unroll
            for (int half = 0; half < 2; half++) {
                const int row_g = row0 + wm * 32 + mf * 16 + (lane >> 2) + half * 8;
                float v0 = acc[mf][nt][half * 2 + 0] + b0;
                float v1 = acc[mf][nt][half * 2 + 1] + b1;
                const size_t o = (size_t)row_g * FD + col_g;
                if (MODE == 0) {
                    g_q[o] = v0; g_q[o + 1] = v1;
                    __nv_bfloat162 p;
                    p.x = __float2bfloat16(v0); p.y = __float2bfloat16(v1);
                    *(__nv_bfloat162*)&g_qb[o] = p;
                } else if (MODE == 1) {
                    v0 = fmaxf(v0, 0.f); v1 = fmaxf(v1, 0.f);
                    __nv_bfloat162 ph, pl;
                    ph.x = __float2bfloat16(v0); ph.y = __float2bfloat16(v1);
                    pl.x = __float2bfloat16(v0 - __bfloat162float(ph.x));
                    pl.y = __float2bfloat16(v1 - __bfloat162float(ph.y));
                    *(__nv_bfloat162*)&g_hhi[o] = ph;
                    *(__nv_bfloat162*)&g_hlo[o] = pl;
                } else {
                    Cout[o] = v0; Cout[o + 1] = v1;
                }
            }
        }
    }
}

// ---------------- sim v3: 64-row tile, 2 CTAs/SM, register-filtered scan ----------------
// block 256 thr (8 warps as 2m x 4n). Row tile 64 (persistent q), key tile 128,
// K chunk 32 double-buffered. simT [row][key] fp32; scan: 4 thr/row, float4 + max filter.
// smem: Aq[64][264] bf16 (33792) + Bs[2][128][40] bf16 (20480) + simT[64][132] f32 (33792)
#define SIM_AQ_OFF   0
#define SIM_BS_OFF   33792
#define SIM_ST_OFF   54272
#define SIM_SMEM     88064

__global__ __launch_bounds__(256, 2)
void sim_topk_kernel() {
    extern __shared__ char dynsmem[];
    __nv_bfloat16* Aq   = (__nv_bfloat16*)(dynsmem + SIM_AQ_OFF);   // [r][264]
    __nv_bfloat16* Bs   = (__nv_bfloat16*)(dynsmem + SIM_BS_OFF);   // [st][key][40]
    float*         simT = (float*)(dynsmem + SIM_ST_OFF);           // [r][132]

    const int tid  = threadIdx.x;
    const int lane = tid & 31;
    const int wid  = tid >> 5;
    const int wm = wid & 1, wn = wid >> 1;      // 2m x 4n
    const int row0 = blockIdx.x * 64;
    const int srow = tid >> 2, qd = tid & 3;    // scan: 4 threads per row

    float ts[8]; int ti[8];
    #pragma unroll
    for (int i = 0; i < 8; i++) { ts[i] = -3.4e38f; ti[i] = 0; }

    // persistent q tile: 64 rows x 256 k
    for (int i = tid; i < 64 * 32; i += 256) {
        const int r = i >> 5, seg = i & 31;
        cp16(&Aq[r * 264 + seg * 8], &g_qb[(size_t)(row0 + r) * FD + seg * 8]);
    }
    // first key chunk (stage 0)
    #pragma unroll
    for (int j = 0; j < 2; j++) {
        const int idx = tid + j * 256;
        const int key = idx >> 2, seg = idx & 3;
        cp16(&Bs[(0 * 128 + key) * 40 + seg * 8], &g_kb[(size_t)key * FD + seg * 8]);
    }
    cp_commit();

    float acc[2][4][4];

    const int NGC = (MSZ / 128) * 8;   // 256 chunks (8 per key tile)
    for (int gc = 0; gc < NGC; gc++) {
        const int st = gc & 1;
        if (gc + 1 < NGC) {
            const int mt2 = (gc + 1) >> 3, kt2 = ((gc + 1) & 7) * 32;
            const int st2 = (gc + 1) & 1;
            #pragma unroll
            for (int j = 0; j < 2; j++) {
                const int idx = tid + j * 256;
                const int key = idx >> 2, seg = idx & 3;
                cp16(&Bs[(st2 * 128 + key) * 40 + seg * 8],
                     &g_kb[(size_t)(mt2 * 128 + key) * FD + kt2 + seg * 8]);
            }
        }
        cp_commit();
        cp_wait1();
        __syncthreads();

        if ((gc & 7) == 0) {
            #pragma unroll
            for (int mf = 0; mf < 2; mf++)
                #pragma unroll
                for (int nt = 0; nt < 4; nt++)
                    #pragma unroll
                    for (int i = 0; i < 4; i++) acc[mf][nt][i] = 0.f;
        }

        const int kbase = (gc & 7) * 32;
        #pragma unroll
        for (int ks = 0; ks < 2; ks++) {
            const int ak = kbase + ks * 16 + (lane & 3) * 2;
            uint32_t a[2][4];
            #pragma unroll
            for (int mf = 0; mf < 2; mf++) {
                const int r = wm * 32 + mf * 16 + (lane >> 2);
                a[mf][0] = *(const uint32_t*)&Aq[r * 264 + ak];
                a[mf][1] = *(const uint32_t*)&Aq[(r + 8) * 264 + ak];
                a[mf][2] = *(const uint32_t*)&Aq[r * 264 + ak + 8];
                a[mf][3] = *(const uint32_t*)&Aq[(r + 8) * 264 + ak + 8];
            }
            const int bk = ks * 16 + (lane & 3) * 2;
            #pragma unroll
            for (int nt = 0; nt < 4; nt++) {
                const int bn = wn * 32 + nt * 8 + (lane >> 2);
                uint32_t b0 = *(const uint32_t*)&Bs[(st * 128 + bn) * 40 + bk];
                uint32_t b1 = *(const uint32_t*)&Bs[(st * 128 + bn) * 40 + bk + 8];
                mma16816(acc[0][nt], a[0][0], a[0][1], a[0][2], a[0][3], b0, b1);
                mma16816(acc[1][nt], a[1][0], a[1][1], a[1][2], a[1][3], b0, b1);
            }
        }

        if ((gc & 7) == 7) {
            const int mt = gc >> 3;
            __syncthreads();
            // store sim tile [row][key]
            #pragma unroll
            for (int nt = 0; nt < 4; nt++) {
                const int key0 = wn * 32 + nt * 8 + (lane & 3) * 2;
                #pragma unroll
                for (int mf = 0; mf < 2; mf++) {
                    const int rw = wm * 32 + mf * 16 + (lane >> 2);
                    float2 p0 = make_float2(acc[mf][nt][0], acc[mf][nt][1]);
                    float2 p1 = make_float2(acc[mf][nt][2], acc[mf][nt][3]);
                    *(float2*)&simT[rw * 132 + key0]       = p0;
                    *(float2*)&simT[(rw + 8) * 132 + key0] = p1;
                }
            }
            __syncthreads();
            // scan: thread (srow, qd) covers keys { qd*4 + i*16 + j : i<8, j<4 }
            #pragma unroll
            for (int i = 0; i < 8; i++) {
                const int k0 = qd * 4 + i * 16;
                float4 v = *(const float4*)&simT[srow * 132 + k0];
                float m01 = fmaxf(v.x, v.y), m23 = fmaxf(v.z, v.w);
                if (fmaxf(m01, m23) > ts[7]) {
                    float vv[4] = {v.x, v.y, v.z, v.w};
                    #pragma unroll
                    for (int j = 0; j < 4; j++) {
                        if (vv[j] > ts[7]) {
                            ts[7] = vv[j]; ti[7] = mt * 128 + k0 + j;
                            #pragma unroll
                            for (int s = 7; s > 0; s--) {
                                if (ts[s] > ts[s - 1]) {
                                    float tf = ts[s]; ts[s] = ts[s - 1]; ts[s - 1] = tf;
                                    int   tt = ti[s]; ti[s] = ti[s - 1]; ti[s - 1] = tt;
                                }
                            }
                        }
                    }
                }
            }
            __syncthreads();
        } else {
            __syncthreads();
        }
    }

    // final merge: 4 partial lists per row -> top-8 (reuse simT as scratch)
    float* cand = simT;   // [tid][16]: 8 vals + 8 idx-bits = 16KB
    #pragma unroll
    for (int i = 0; i < 8; i++) {
        cand[tid * 16 + i]     = ts[i];
        cand[tid * 16 + 8 + i] = __int_as_float(ti[i]);
    }
    __syncthreads();
    if (qd == 0) {
        #pragma unroll
        for (int other = 1; other < 4; other++) {
            const int ot = tid + other;
            #pragma unroll
            for (int i = 0; i < 8; i++) {
                float v = cand[ot * 16 + i];
                int  ix = __float_as_int(cand[ot * 16 + 8 + i]);
                if (v > ts[7]) {
                    ts[7] = v; ti[7] = ix;
                    #pragma unroll
                    for (int s = 7; s > 0; s--) {
                        if (ts[s] > ts[s - 1]) {
                            float tf = ts[s]; ts[s] = ts[s - 1]; ts[s - 1] = tf;
                            int   tt = ti[s]; ti[s] = ti[s - 1]; ti[s - 1] = tt;
                        }
                    }
                }
            }
        }
        #pragma unroll
        for (int i = 0; i < 8; i++)
            g_idx[(size_t)(row0 + srow) * TOPK + i] = ti[i];
    }
}

// ---------------- exact fp32 re-score + softmax + weighted gather ----------------
__global__ __launch_bounds__(256)
void retrieve_kernel(const float* __restrict__ keys, const float* __restrict__ vals) {
    const int gwarp = (int)((blockIdx.x * blockDim.x + threadIdx.x) >> 5);
    const int lane  = threadIdx.x & 31;
    if (gwarp >= TOKENS) return;

    const float* qrow = g_q + (size_t)gwarp * FD;
    float4 q1 = *(const float4*)&qrow[lane * 8];
    float4 q2 = *(const float4*)&qrow[lane * 8 + 4];

    int id[8];
    #pragma unroll
    for (int i = 0; i < 8; i++) id[i] = g_idx[(size_t)gwarp * TOPK + i];

    float s[8];
    #pragma unroll
    for (int i = 0; i < 8; i++) {
        const float* kr = keys + (size_t)id[i] * FD + lane * 8;
        float4 k1 = *(const float4*)&kr[0];
        float4 k2 = *(const float4*)&kr[4];
        float p = q1.x * k1.x + q1.y * k1.y + q1.z * k1.z + q1.w * k1.w
                + q2.x * k2.x + q2.y * k2.y + q2.z * k2.z + q2.w * k2.w;
        #pragma unroll
        for (int o = 16; o > 0; o >>= 1) p += __shfl_xor_sync(0xffffffffu, p, o);
        s[i] = p;
    }
    float mx = s[0];
    #pragma unroll
    for (int i = 1; i < 8; i++) mx = fmaxf(mx, s[i]);
    float z = 0.f;
    #pragma unroll
    for (int i = 0; i < 8; i++) { s[i] = __expf(s[i] - mx); z += s[i]; }
    const float rz = 1.f / z;

    float r[8];
    #pragma unroll
    for (int j = 0; j < 8; j++) r[j] = 0.f;
    #pragma unroll
    for (int i = 0; i < 8; i++) {
        const float w = s[i] * rz;
        const float* vr = vals + (size_t)id[i] * FD + lane * 8;
        float4 v1 = *(const float4*)&vr[0];
        float4 v2 = *(const float4*)&vr[4];
        r[0] = fmaf(w, v1.x, r[0]); r[1] = fmaf(w, v1.y, r[1]);
        r[2] = fmaf(w, v1.z, r[2]); r[3] = fmaf(w, v1.w, r[3]);
        r[4] = fmaf(w, v2.x, r[4]); r[5] = fmaf(w, v2.y, r[5]);
        r[6] = fmaf(w, v2.z, r[6]); r[7] = fmaf(w, v2.w, r[7]);
    }
    __nv_bfloat16 hv[8], lv[8];
    #pragma unroll
    for (int j = 0; j < 8; j++) {
        hv[j] = __float2bfloat16(r[j]);
        lv[j] = __float2bfloat16(r[j] - __bfloat162float(hv[j]));
    }
    const size_t off = (size_t)gwarp * FD + lane * 8;
    *(uint4*)&g_rhi[off] = *(uint4*)hv;
    *(uint4*)&g_rlo[off] = *(uint4*)lv;
}

// ---------------- launch ----------------
extern "C" void kernel_launch(void* const* d_in, const int* in_sizes, int n_in,
                              void* d_out, int out_size) {
    const float* query = (const float*)d_in[0];
    const float* mkeys = (const float*)d_in[1];
    const float* mvals = (const float*)d_in[2];
    const float* Wq    = (const float*)d_in[3];
    const float* bq    = (const float*)d_in[4];
    const float* W1    = (const float*)d_in[5];
    const float* b1    = (const float*)d_in[6];
    const float* W2    = (const float*)d_in[7];
    const float* b2    = (const float*)d_in[8];
    float* out = (float*)d_out;

    cudaFuncSetAttribute(sim_topk_kernel, cudaFuncAttributeMaxDynamicSharedMemorySize, SIM_SMEM);
    cudaFuncSetAttribute(bgemm<0>, cudaFuncAttributeMaxDynamicSharedMemorySize, BG_SMEM);
    cudaFuncSetAttribute(bgemm<1>, cudaFuncAttributeMaxDynamicSharedMemorySize, BG_SMEM);
    cudaFuncSetAttribute(bgemm<2>, cudaFuncAttributeMaxDynamicSharedMemorySize, BG_SMEM);

    // launch order keeps sim_topk at index 3 (ncu capture slot)
    cvt_kw_kernel<<<(MSZ * FD + 4 * FD * FD + 255) / 256, 256>>>(mkeys, Wq, W1, W2);   // 0
    cvt_query_split_kernel<<<(TOKENS * FD + 255) / 256, 256>>>(query);                 // 1
    bgemm<0><<<dim3(2, 512), 256, BG_SMEM>>>(bq, nullptr);                             // 2
    sim_topk_kernel<<<TOKENS / 64, 256, SIM_SMEM>>>();                                 // 3
    retrieve_kernel<<<(TOKENS * 32) / 256, 256>>>(mkeys, mvals);                       // 4
    bgemm<1><<<dim3(2, 512), 256, BG_SMEM>>>(b1, nullptr);                             // 5
    bgemm<2><<<dim3(2, 512), 256, BG_SMEM>>>(b2, out);                                 // 6
}

// round 13
// speedup vs baseline: 1.8233x; 1.0692x over previous
#include <cuda_runtime.h>
#include <cuda_bf16.h>
#include <stdint.h>

#define TOKENS 65536   // B*N = 16*4096
#define FD     256
#define MSZ    4096
#define TOPK   8

// ---------------- device scratch (referenced ONLY from device code) ----------------
__device__ float          g_q   [TOKENS * FD];   // projected q, fp32 (exact rescore)
__device__ __nv_bfloat16  g_qb  [TOKENS * FD];   // projected q, bf16 (MMA ranking)
__device__ __nv_bfloat16  g_kb  [MSZ * FD];      // memory_keys bf16
__device__ int            g_idx [TOKENS * TOPK]; // top-8 indices per row
__device__ __nv_bfloat16  g_xhi [TOKENS * FD];   // raw query hi
__device__ __nv_bfloat16  g_xlo [TOKENS * FD];   // raw query lo
__device__ __nv_bfloat16  g_rhi [TOKENS * FD];   // retrieved hi
__device__ __nv_bfloat16  g_rlo [TOKENS * FD];   // retrieved lo
__device__ __nv_bfloat16  g_hhi [TOKENS * FD];   // hidden (relu) hi
__device__ __nv_bfloat16  g_hlo [TOKENS * FD];   // hidden (relu) lo
__device__ __nv_bfloat16  g_WqThi[FD * FD],     g_WqTlo[FD * FD];       // [n][k]
__device__ __nv_bfloat16  g_W1Thi[FD * 2 * FD], g_W1Tlo[FD * 2 * FD];   // [n][k], k=512
__device__ __nv_bfloat16  g_W2Thi[FD * FD],     g_W2Tlo[FD * FD];       // [n][k]

// ---------------- cp.async / ldmatrix helpers ----------------
__device__ __forceinline__ void cp16(void* sdst, const void* gsrc) {
    uint32_t s = (uint32_t)__cvta_generic_to_shared(sdst);
    asm volatile("cp.async.cg.shared.global [%0], [%1], 16;\n" :: "r"(s), "l"(gsrc));
}
__device__ __forceinline__ void cp_commit() {
    asm volatile("cp.async.commit_group;\n" ::: "memory");
}
__device__ __forceinline__ void cp_wait1() {
    asm volatile("cp.async.wait_group 1;\n" ::: "memory");
}
__device__ __forceinline__ void ldsm4(uint32_t* r, const void* p) {
    uint32_t a = (uint32_t)__cvta_generic_to_shared(p);
    asm volatile("ldmatrix.sync.aligned.m8n8.x4.shared.b16 {%0,%1,%2,%3}, [%4];"
                 : "=r"(r[0]), "=r"(r[1]), "=r"(r[2]), "=r"(r[3]) : "r"(a));
}

// ---------------- conversions ----------------
__global__ __launch_bounds__(256)
void cvt_kw_kernel(const float* __restrict__ mk, const float* __restrict__ Wq,
                   const float* __restrict__ W1, const float* __restrict__ W2) {
    int i = blockIdx.x * blockDim.x + threadIdx.x;
    if (i < MSZ * FD) {
        g_kb[i] = __float2bfloat16(mk[i]);
        return;
    }
    int j = i - MSZ * FD;
    const float* W; __nv_bfloat16 *hiT, *loT; int K;
    if (j < FD * FD)          { W = Wq; hiT = g_WqThi; loT = g_WqTlo; K = FD; }
    else if (j < 3 * FD * FD) { j -= FD * FD; W = W1; hiT = g_W1Thi; loT = g_W1Tlo; K = 2 * FD; }
    else if (j < 4 * FD * FD) { j -= 3 * FD * FD; W = W2; hiT = g_W2Thi; loT = g_W2Tlo; K = FD; }
    else return;
    int n = j / K, k = j - n * K;
    float x = W[(size_t)k * FD + n];
    __nv_bfloat16 h = __float2bfloat16(x);
    hiT[j] = h;
    loT[j] = __float2bfloat16(x - __bfloat162float(h));
}

__global__ __launch_bounds__(256)
void cvt_query_split_kernel(const float* __restrict__ src) {
    int i = blockIdx.x * blockDim.x + threadIdx.x;
    if (i < TOKENS * FD) {
        float x = src[i];
        __nv_bfloat16 h = __float2bfloat16(x);
        g_xhi[i] = h;
        g_xlo[i] = __float2bfloat16(x - __bfloat162float(h));
    }
}

// ---------------- mma helper ----------------
__device__ __forceinline__ void mma16816(float* d, uint32_t a0, uint32_t a1,
                                         uint32_t a2, uint32_t a3,
                                         uint32_t b0, uint32_t b1) {
    asm volatile(
        "mma.sync.aligned.m16n8k16.row.col.f32.bf16.bf16.f32 "
        "{%0,%1,%2,%3}, {%4,%5,%6,%7}, {%8,%9}, {%0,%1,%2,%3};\n"
        : "+f"(d[0]), "+f"(d[1]), "+f"(d[2]), "+f"(d[3])
        : "r"(a0), "r"(a1), "r"(a2), "r"(a3), "r"(b0), "r"(b1));
}

// ---------------- split-bf16 tensor-core GEMM, 2-stage cp.async, ldmatrix ----------------
#define BG_SMEM 81920

template<int MODE>
__device__ __forceinline__ void bgemm_load_chunk(__nv_bfloat16* As, __nv_bfloat16* Bs,
                                                 int st, int kt, int row0, int col0,
                                                 int tid, int Ktot) {
    const __nv_bfloat16 *ah, *al;
    int kof;
    if (MODE == 1 && kt >= 256) { ah = g_rhi; al = g_rlo; kof = kt - 256; }
    else if (MODE == 2)         { ah = g_hhi; al = g_hlo; kof = kt; }
    else                        { ah = g_xhi; al = g_xlo; kof = kt; }
    const __nv_bfloat16* bh = (MODE == 0) ? g_WqThi : (MODE == 1) ? g_W1Thi : g_W2Thi;
    const __nv_bfloat16* bl = (MODE == 0) ? g_WqTlo : (MODE == 1) ? g_W1Tlo : g_W2Tlo;
    const int lr = tid >> 1, lk = (tid & 1) * 16;
    const size_t aoff = (size_t)(row0 + lr) * FD + kof + lk;
    const size_t boff = (size_t)(col0 + lr) * Ktot + kt + lk;
    cp16(&As[((st * 2 + 0) * 128 + lr) * 40 + lk],     &ah[aoff]);
    cp16(&As[((st * 2 + 0) * 128 + lr) * 40 + lk + 8], &ah[aoff + 8]);
    cp16(&As[((st * 2 + 1) * 128 + lr) * 40 + lk],     &al[aoff]);
    cp16(&As[((st * 2 + 1) * 128 + lr) * 40 + lk + 8], &al[aoff + 8]);
    cp16(&Bs[((st * 2 + 0) * 128 + lr) * 40 + lk],     &bh[boff]);
    cp16(&Bs[((st * 2 + 0) * 128 + lr) * 40 + lk + 8], &bh[boff + 8]);
    cp16(&Bs[((st * 2 + 1) * 128 + lr) * 40 + lk],     &bl[boff]);
    cp16(&Bs[((st * 2 + 1) * 128 + lr) * 40 + lk + 8], &bl[boff + 8]);
}

template<int MODE>
__global__ __launch_bounds__(256, 2)
void bgemm(const float* __restrict__ bias, float* __restrict__ Cout) {
    extern __shared__ char dynsmem[];
    __nv_bfloat16* As = (__nv_bfloat16*)dynsmem;
    __nv_bfloat16* Bs = As + 2 * 2 * 128 * 40;

    const int tid  = threadIdx.x;
    const int lane = tid & 31;
    const int wid  = tid >> 5;
    const int wm = wid & 3, wn = wid >> 2;
    const int row0 = blockIdx.y * 128;
    const int col0 = blockIdx.x * 128;
    const int Ktot = (MODE == 1) ? 512 : 256;
    const int NC   = Ktot / 32;

    // ldmatrix lane address components
    const int lrow = (lane & 7) + ((lane >> 3) & 1) * 8;  // row within 16 (j&1)
    const int lcol = (lane >> 4) * 8;                     // col offset 0/8 (j>>1)
    const int brow = (lane & 7) + (lane >> 4) * 8;        // B: row within 16 (j>>1)
    const int bcol = ((lane >> 3) & 1) * 8;               // B: col offset (j&1)

    float acc[2][8][4];
    #pragma unroll
    for (int mf = 0; mf < 2; mf++)
        #pragma unroll
        for (int nt = 0; nt < 8; nt++)
            #pragma unroll
            for (int i = 0; i < 4; i++) acc[mf][nt][i] = 0.f;

    bgemm_load_chunk<MODE>(As, Bs, 0, 0, row0, col0, tid, Ktot);
    cp_commit();

    for (int c = 0; c < NC; c++) {
        const int st = c & 1;
        if (c + 1 < NC)
            bgemm_load_chunk<MODE>(As, Bs, (c + 1) & 1, (c + 1) * 32, row0, col0, tid, Ktot);
        cp_commit();
        cp_wait1();
        __syncthreads();

        const int sH = (st * 2 + 0) * 128, sL = (st * 2 + 1) * 128;
        #pragma unroll
        for (int ks = 0; ks < 2; ks++) {
            const int k0 = ks * 16;
            uint32_t fah[2][4], fal[2][4];
            #pragma unroll
            for (int mf = 0; mf < 2; mf++) {
                const int r = wm * 32 + mf * 16 + lrow;
                ldsm4(fah[mf], &As[(sH + r) * 40 + k0 + lcol]);
                ldsm4(fal[mf], &As[(sL + r) * 40 + k0 + lcol]);
            }
            #pragma unroll
            for (int p = 0; p < 4; p++) {            // nt pair (2p, 2p+1)
                const int n0 = wn * 64 + p * 16 + brow;
                uint32_t fbh[4], fbl[4];
                ldsm4(fbh, &Bs[(sH + n0) * 40 + k0 + bcol]);
                ldsm4(fbl, &Bs[(sL + n0) * 40 + k0 + bcol]);
                #pragma unroll
                for (int half = 0; half < 2; half++) {
                    const int nt = 2 * p + half;
                    uint32_t bh0 = fbh[half * 2], bh1 = fbh[half * 2 + 1];
                    uint32_t bl0 = fbl[half * 2], bl1 = fbl[half * 2 + 1];
                    #pragma unroll
                    for (int mf = 0; mf < 2; mf++) {
                        mma16816(acc[mf][nt], fah[mf][0], fah[mf][1], fah[mf][2], fah[mf][3], bh0, bh1);
                        mma16816(acc[mf][nt], fah[mf][0], fah[mf][1], fah[mf][2], fah[mf][3], bl0, bl1);
                        mma16816(acc[mf][nt], fal[mf][0], fal[mf][1], fal[mf][2], fal[mf][3], bh0, bh1);
                    }
                }
            }
        }
        __syncthreads();
    }

    #pragma unroll
    for (int nt = 0; nt < 8; nt++) {
        const int col_g = col0 + wn * 64 + nt * 8 + (lane & 3) * 2;
        const float b0 = bias[col_g], b1 = bias[col_g + 1];
        #pragma unroll
        for (int mf = 0; mf < 2; mf++) {
            #pragma unroll
            for (int half = 0; half < 2; half++) {
                const int row_g = row0 + wm * 32 + mf * 16 + (lane >> 2) + half * 8;
                float v0 = acc[mf][nt][half * 2 + 0] + b0;
                float v1 = acc[mf][nt][half * 2 + 1] + b1;
                const size_t o = (size_t)row_g * FD + col_g;
                if (MODE == 0) {
                    g_q[o] = v0; g_q[o + 1] = v1;
                    __nv_bfloat162 p;
                    p.x = __float2bfloat16(v0); p.y = __float2bfloat16(v1);
                    *(__nv_bfloat162*)&g_qb[o] = p;
                } else if (MODE == 1) {
                    v0 = fmaxf(v0, 0.f); v1 = fmaxf(v1, 0.f);
                    __nv_bfloat162 ph, pl;
                    ph.x = __float2bfloat16(v0); ph.y = __float2bfloat16(v1);
                    pl.x = __float2bfloat16(v0 - __bfloat162float(ph.x));
                    pl.y = __float2bfloat16(v1 - __bfloat162float(ph.y));
                    *(__nv_bfloat162*)&g_hhi[o] = ph;
                    *(__nv_bfloat162*)&g_hlo[o] = pl;
                } else {
                    Cout[o] = v0; Cout[o + 1] = v1;
                }
            }
        }
    }
}

// ---------------- sim v4: 64-row tile, 2 CTAs/SM, ldmatrix fragments ----------------
#define SIM_AQ_OFF   0
#define SIM_BS_OFF   33792
#define SIM_ST_OFF   54272
#define SIM_SMEM     88064

__global__ __launch_bounds__(256, 2)
void sim_topk_kernel() {
    extern __shared__ char dynsmem[];
    __nv_bfloat16* Aq   = (__nv_bfloat16*)(dynsmem + SIM_AQ_OFF);   // [r][264]
    __nv_bfloat16* Bs   = (__nv_bfloat16*)(dynsmem + SIM_BS_OFF);   // [st][key][40]
    float*         simT = (float*)(dynsmem + SIM_ST_OFF);           // [r][132]

    const int tid  = threadIdx.x;
    const int lane = tid & 31;
    const int wid  = tid >> 5;
    const int wm = wid & 1, wn = wid >> 1;      // 2m x 4n
    const int row0 = blockIdx.x * 64;
    const int srow = tid >> 2, qd = tid & 3;    // scan: 4 threads per row

    // ldmatrix lane address components
    const int lrow = (lane & 7) + ((lane >> 3) & 1) * 8;
    const int lcol = (lane >> 4) * 8;
    const int brow = (lane & 7) + (lane >> 4) * 8;
    const int bcol = ((lane >> 3) & 1) * 8;

    float ts[8]; int ti[8];
    #pragma unroll
    for (int i = 0; i < 8; i++) { ts[i] = -3.4e38f; ti[i] = 0; }

    // persistent q tile: 64 rows x 256 k
    for (int i = tid; i < 64 * 32; i += 256) {
        const int r = i >> 5, seg = i & 31;
        cp16(&Aq[r * 264 + seg * 8], &g_qb[(size_t)(row0 + r) * FD + seg * 8]);
    }
    // first key chunk (stage 0)
    #pragma unroll
    for (int j = 0; j < 2; j++) {
        const int idx = tid + j * 256;
        const int key = idx >> 2, seg = idx & 3;
        cp16(&Bs[(0 * 128 + key) * 40 + seg * 8], &g_kb[(size_t)key * FD + seg * 8]);
    }
    cp_commit();

    float acc[2][4][4];

    const int NGC = (MSZ / 128) * 8;   // 256 chunks (8 per key tile)
    for (int gc = 0; gc < NGC; gc++) {
        const int st = gc & 1;
        if (gc + 1 < NGC) {
            const int mt2 = (gc + 1) >> 3, kt2 = ((gc + 1) & 7) * 32;
            const int st2 = (gc + 1) & 1;
            #pragma unroll
            for (int j = 0; j < 2; j++) {
                const int idx = tid + j * 256;
                const int key = idx >> 2, seg = idx & 3;
                cp16(&Bs[(st2 * 128 + key) * 40 + seg * 8],
                     &g_kb[(size_t)(mt2 * 128 + key) * FD + kt2 + seg * 8]);
            }
        }
        cp_commit();
        cp_wait1();
        __syncthreads();

        if ((gc & 7) == 0) {
            #pragma unroll
            for (int mf = 0; mf < 2; mf++)
                #pragma unroll
                for (int nt = 0; nt < 4; nt++)
                    #pragma unroll
                    for (int i = 0; i < 4; i++) acc[mf][nt][i] = 0.f;
        }

        const int kbase = (gc & 7) * 32;
        #pragma unroll
        for (int ks = 0; ks < 2; ks++) {
            const int ak0 = kbase + ks * 16;
            const int bk0 = ks * 16;
            uint32_t a[2][4];
            #pragma unroll
            for (int mf = 0; mf < 2; mf++) {
                const int r = wm * 32 + mf * 16 + lrow;
                ldsm4(a[mf], &Aq[r * 264 + ak0 + lcol]);
            }
            #pragma unroll
            for (int t = 0; t < 2; t++) {            // nt pair (2t, 2t+1)
                const int n0 = wn * 32 + t * 16 + brow;
                uint32_t fb[4];
                ldsm4(fb, &Bs[(st * 128 + n0) * 40 + bk0 + bcol]);
                #pragma unroll
                for (int half = 0; half < 2; half++) {
                    const int nt = 2 * t + half;
                    uint32_t b0 = fb[half * 2], b1 = fb[half * 2 + 1];
                    mma16816(acc[0][nt], a[0][0], a[0][1], a[0][2], a[0][3], b0, b1);
                    mma16816(acc[1][nt], a[1][0], a[1][1], a[1][2], a[1][3], b0, b1);
                }
            }
        }

        if ((gc & 7) == 7) {
            const int mt = gc >> 3;
            __syncthreads();
            // store sim tile [row][key]
            #pragma unroll
            for (int nt = 0; nt < 4; nt++) {
                const int key0 = wn * 32 + nt * 8 + (lane & 3) * 2;
                #pragma unroll
                for (int mf = 0; mf < 2; mf++) {
                    const int rw = wm * 32 + mf * 16 + (lane >> 2);
                    float2 p0 = make_float2(acc[mf][nt][0], acc[mf][nt][1]);
                    float2 p1 = make_float2(acc[mf][nt][2], acc[mf][nt][3]);
                    *(float2*)&simT[rw * 132 + key0]       = p0;
                    *(float2*)&simT[(rw + 8) * 132 + key0] = p1;
                }
            }
            __syncthreads();
            // scan: thread (srow, qd) covers keys { qd*4 + i*16 + j : i<8, j<4 }
            #pragma unroll
            for (int i = 0; i < 8; i++) {
                const int k0 = qd * 4 + i * 16;
                float4 v = *(const float4*)&simT[srow * 132 + k0];
                float m01 = fmaxf(v.x, v.y), m23 = fmaxf(v.z, v.w);
                if (fmaxf(m01, m23) > ts[7]) {
                    float vv[4] = {v.x, v.y, v.z, v.w};
                    #pragma unroll
                    for (int j = 0; j < 4; j++) {
                        if (vv[j] > ts[7]) {
                            ts[7] = vv[j]; ti[7] = mt * 128 + k0 + j;
                            #pragma unroll
                            for (int s = 7; s > 0; s--) {
                                if (ts[s] > ts[s - 1]) {
                                    float tf = ts[s]; ts[s] = ts[s - 1]; ts[s - 1] = tf;
                                    int   tt = ti[s]; ti[s] = ti[s - 1]; ti[s - 1] = tt;
                                }
                            }
                        }
                    }
                }
            }
            __syncthreads();
        } else {
            __syncthreads();
        }
    }

    // final merge: 4 partial lists per row -> top-8 (reuse simT as scratch)
    float* cand = simT;
    #pragma unroll
    for (int i = 0; i < 8; i++) {
        cand[tid * 16 + i]     = ts[i];
        cand[tid * 16 + 8 + i] = __int_as_float(ti[i]);
    }
    __syncthreads();
    if (qd == 0) {
        #pragma unroll
        for (int other = 1; other < 4; other++) {
            const int ot = tid + other;
            #pragma unroll
            for (int i = 0; i < 8; i++) {
                float v = cand[ot * 16 + i];
                int  ix = __float_as_int(cand[ot * 16 + 8 + i]);
                if (v > ts[7]) {
                    ts[7] = v; ti[7] = ix;
                    #pragma unroll
                    for (int s = 7; s > 0; s--) {
                        if (ts[s] > ts[s - 1]) {
                            float tf = ts[s]; ts[s] = ts[s - 1]; ts[s - 1] = tf;
                            int   tt = ti[s]; ti[s] = ti[s - 1]; ti[s - 1] = tt;
                        }
                    }
                }
            }
        }
        #pragma unroll
        for (int i = 0; i < 8; i++)
            g_idx[(size_t)(row0 + srow) * TOPK + i] = ti[i];
    }
}

// ---------------- exact fp32 re-score + softmax + weighted gather ----------------
__global__ __launch_bounds__(256)
void retrieve_kernel(const float* __restrict__ keys, const float* __restrict__ vals) {
    const int gwarp = (int)((blockIdx.x * blockDim.x + threadIdx.x) >> 5);
    const int lane  = threadIdx.x & 31;
    if (gwarp >= TOKENS) return;

    const float* qrow = g_q + (size_t)gwarp * FD;
    float4 q1 = *(const float4*)&qrow[lane * 8];
    float4 q2 = *(const float4*)&qrow[lane * 8 + 4];

    int id[8];
    #pragma unroll
    for (int i = 0; i < 8; i++) id[i] = g_idx[(size_t)gwarp * TOPK + i];

    float s[8];
    #pragma unroll
    for (int i = 0; i < 8; i++) {
        const float* kr = keys + (size_t)id[i] * FD + lane * 8;
        float4 k1 = *(const float4*)&kr[0];
        float4 k2 = *(const float4*)&kr[4];
        float p = q1.x * k1.x + q1.y * k1.y + q1.z * k1.z + q1.w * k1.w
                + q2.x * k2.x + q2.y * k2.y + q2.z * k2.z + q2.w * k2.w;
        #pragma unroll
        for (int o = 16; o > 0; o >>= 1) p += __shfl_xor_sync(0xffffffffu, p, o);
        s[i] = p;
    }
    float mx = s[0];
    #pragma unroll
    for (int i = 1; i < 8; i++) mx = fmaxf(mx, s[i]);
    float z = 0.f;
    #pragma unroll
    for (int i = 0; i < 8; i++) { s[i] = __expf(s[i] - mx); z += s[i]; }
    const float rz = 1.f / z;

    float r[8];
    #pragma unroll
    for (int j = 0; j < 8; j++) r[j] = 0.f;
    #pragma unroll
    for (int i = 0; i < 8; i++) {
        const float w = s[i] * rz;
        const float* vr = vals + (size_t)id[i] * FD + lane * 8;
        float4 v1 = *(const float4*)&vr[0];
        float4 v2 = *(const float4*)&vr[4];
        r[0] = fmaf(w, v1.x, r[0]); r[1] = fmaf(w, v1.y, r[1]);
        r[2] = fmaf(w, v1.z, r[2]); r[3] = fmaf(w, v1.w, r[3]);
        r[4] = fmaf(w, v2.x, r[4]); r[5] = fmaf(w, v2.y, r[5]);
        r[6] = fmaf(w, v2.z, r[6]); r[7] = fmaf(w, v2.w, r[7]);
    }
    __nv_bfloat16 hv[8], lv[8];
    #pragma unroll
    for (int j = 0; j < 8; j++) {
        hv[j] = __float2bfloat16(r[j]);
        lv[j] = __float2bfloat16(r[j] - __bfloat162float(hv[j]));
    }
    const size_t off = (size_t)gwarp * FD + lane * 8;
    *(uint4*)&g_rhi[off] = *(uint4*)hv;
    *(uint4*)&g_rlo[off] = *(uint4*)lv;
}

// ---------------- launch ----------------
extern "C" void kernel_launch(void* const* d_in, const int* in_sizes, int n_in,
                              void* d_out, int out_size) {
    const float* query = (const float*)d_in[0];
    const float* mkeys = (const float*)d_in[1];
    const float* mvals = (const float*)d_in[2];
    const float* Wq    = (const float*)d_in[3];
    const float* bq    = (const float*)d_in[4];
    const float* W1    = (const float*)d_in[5];
    const float* b1    = (const float*)d_in[6];
    const float* W2    = (const float*)d_in[7];
    const float* b2    = (const float*)d_in[8];
    float* out = (float*)d_out;

    cudaFuncSetAttribute(sim_topk_kernel, cudaFuncAttributeMaxDynamicSharedMemorySize, SIM_SMEM);
    cudaFuncSetAttribute(bgemm<0>, cudaFuncAttributeMaxDynamicSharedMemorySize, BG_SMEM);
    cudaFuncSetAttribute(bgemm<1>, cudaFuncAttributeMaxDynamicSharedMemorySize, BG_SMEM);
    cudaFuncSetAttribute(bgemm<2>, cudaFuncAttributeMaxDynamicSharedMemorySize, BG_SMEM);

    // launch order keeps sim_topk at index 3 (ncu capture slot)
    cvt_kw_kernel<<<(MSZ * FD + 4 * FD * FD + 255) / 256, 256>>>(mkeys, Wq, W1, W2);   // 0
    cvt_query_split_kernel<<<(TOKENS * FD + 255) / 256, 256>>>(query);                 // 1
    bgemm<0><<<dim3(2, 512), 256, BG_SMEM>>>(bq, nullptr);                             // 2
    sim_topk_kernel<<<TOKENS / 64, 256, SIM_SMEM>>>();                                 // 3
    retrieve_kernel<<<(TOKENS * 32) / 256, 256>>>(mkeys, mvals);                       // 4
    bgemm<1><<<dim3(2, 512), 256, BG_SMEM>>>(b1, nullptr);                             // 5
    bgemm<2><<<dim3(2, 512), 256, BG_SMEM>>>(b2, out);                                 // 6
}